// round 10
// baseline (speedup 1.0000x reference)
#include <cuda_runtime.h>
#include <cuda_bf16.h>
#include <cstdint>
#include <math.h>

#define NEG_INF_F   (-9.0e15f)

extern __shared__ char dyn_smem[];

// ============================================================================
// Helpers
// ============================================================================
__device__ __forceinline__ uint32_t s2u(const void* p) {
    uint32_t a;
    asm("{ .reg .u64 t; cvta.to.shared.u64 t, %1; cvt.u32.u64 %0, t; }"
        : "=r"(a) : "l"(p));
    return a;
}
__device__ __forceinline__ void ldm_x4(uint32_t* r, uint32_t addr) {
    asm volatile("ldmatrix.sync.aligned.m8n8.x4.shared.b16 {%0,%1,%2,%3}, [%4];"
                 : "=r"(r[0]), "=r"(r[1]), "=r"(r[2]), "=r"(r[3]) : "r"(addr));
}
__device__ __forceinline__ void mma16816(float* c, const uint32_t* a, const uint32_t* b) {
    asm volatile(
        "mma.sync.aligned.m16n8k16.row.col.f32.bf16.bf16.f32 "
        "{%0,%1,%2,%3}, {%4,%5,%6,%7}, {%8,%9}, {%0,%1,%2,%3};"
        : "+f"(c[0]), "+f"(c[1]), "+f"(c[2]), "+f"(c[3])
        : "r"(a[0]), "r"(a[1]), "r"(a[2]), "r"(a[3]), "r"(b[0]), "r"(b[1]));
}
__device__ __forceinline__ uint32_t pack_bf2(float a, float b) {
    __nv_bfloat162 t = __floats2bfloat162_rn(a, b);
    return *(uint32_t*)&t;
}
// Packed fp32 pair math (Blackwell f32x2; baseline sm_100+ PTX)
__device__ __forceinline__ unsigned long long mul2(unsigned long long a,
                                                   unsigned long long b) {
    unsigned long long d;
    asm("mul.rn.f32x2 %0, %1, %2;" : "=l"(d) : "l"(a), "l"(b));
    return d;
}
__device__ __forceinline__ unsigned long long fma2(unsigned long long a,
                                                   unsigned long long b,
                                                   unsigned long long c) {
    unsigned long long d;
    asm("fma.rn.f32x2 %0, %1, %2, %3;" : "=l"(d) : "l"(a), "l"(b), "l"(c));
    return d;
}
__device__ __forceinline__ float pairsum(unsigned long long v) {
    float2 f = *(float2*)&v;
    return f.x + f.y;
}

// ============================================================================
// Device scratch: B^T in bf16 hi/lo, K padded to 1024 (zeros). Bt[n][k]=B[k][n]
// ============================================================================
__device__ __nv_bfloat16 g_Bh[128 * 1024];
__device__ __nv_bfloat16 g_Bl[128 * 1024];

__global__ void __launch_bounds__(256) bconv_kernel(const float* __restrict__ B) {
    int idx = blockIdx.x * 256 + threadIdx.x;   // 131072
    int n = idx & 127;          // innermost -> coalesced reads of B[k][n]
    int k = idx >> 7;
    float v = (k < 1000) ? B[k * 128 + n] : 0.f;
    __nv_bfloat16 h = __float2bfloat16(v);
    g_Bh[n * 1024 + k] = h;
    g_Bl[n * 1024 + k] = __float2bfloat16(v - __bfloat162float(h));
}

// ============================================================================
// Fused kernel: blockIdx.x < NGB -> attr GEMM tile; else attn block.
//   GEMM: C[8192,128] = A[8192,1000] @ B, bf16 split (AhBh+AlBh+AhBl),
//         BM=64, 8 warps 2x4, warp tile 32x32, single-stage smem (55KB).
//   attn: grid slice (64 batches x 8 i-tiles of 16 rows), 256 thr as (128,2),
//         f32x2-packed score loop, lrelu(p)=0.6p+0.4|p|.
// ============================================================================
#define NGB    128
#define NAB    512
#define GK     1000
#define CH     64
#define NCH    16
#define PITCH  144
#define SA_H   0
#define SA_L   (64 * PITCH)
#define SB_H   (2 * 64 * PITCH)
#define SB_L   (SB_H + 128 * PITCH)
#define SMEM_GEMM (SB_L + 128 * PITCH)      // 55296
#define HST    132
#define SMEM_ATTN ((128 * HST + 4 * HST + 256 + 8) * 4)   // 70752
#define SMEM_FUSED SMEM_ATTN

__global__ void __launch_bounds__(256)
fused_kernel(const float* __restrict__ A,       // A_attr [8192,1000]
             float*       __restrict__ C,       // attr out [8192,128]
             const float* __restrict__ hidden,  // [64,128,128]
             const int*   __restrict__ adj,     // [64,128,128]
             const float* __restrict__ a,       // [128,4]
             float*       __restrict__ out)     // attn out [64,128,128]
{
    const int tid = threadIdx.x;

    if (blockIdx.x < NGB) {
        // ==================== GEMM branch ====================
        char* smem = dyn_smem;
        const uint32_t sb = s2u(smem);
        const int wid  = tid >> 5;
        const int lane = tid & 31;
        const int bm   = blockIdx.x * 64;
        const int wm = wid >> 2;
        const int wn = wid & 3;

        const uint32_t aOff = (uint32_t)((lane & 15) * PITCH + (lane >> 4) * 16);
        const uint32_t bOff = (uint32_t)(((((lane >> 4) & 1) << 3) + (lane & 7)) * PITCH
                                         + ((lane >> 3) & 1) * 16);

        const int arow = tid >> 2, akseg = tid & 3;
        const int brow = tid >> 1, bseg  = tid & 1;
        const float* aptr = A + (size_t)(bm + arow) * GK;
        const __nv_bfloat16* bhp = g_Bh + brow * 1024 + bseg * 32;
        const __nv_bfloat16* blp = g_Bl + brow * 1024 + bseg * 32;

        float  as[16];
        uint4  bh4[4], bl4[4];

        {
            const float4* ap4 = (const float4*)(aptr + akseg * 16);
            #pragma unroll
            for (int i = 0; i < 4; i++) {
                float4 v = ap4[i];
                as[4*i+0] = v.x; as[4*i+1] = v.y; as[4*i+2] = v.z; as[4*i+3] = v.w;
            }
            #pragma unroll
            for (int i = 0; i < 4; i++) {
                bh4[i] = *(const uint4*)(bhp + i * 8);
                bl4[i] = *(const uint4*)(blp + i * 8);
            }
        }

        float acc[2][4][4];
        #pragma unroll
        for (int mt = 0; mt < 2; mt++)
            #pragma unroll
            for (int nt = 0; nt < 4; nt++)
                #pragma unroll
                for (int q = 0; q < 4; q++) acc[mt][nt][q] = 0.f;

        #pragma unroll 1
        for (int c = 0; c < NCH; c++) {
            if (c > 0) __syncthreads();

            {
                char* pa = smem + SA_H + arow * PITCH + akseg * 32;
                char* pl = smem + SA_L + arow * PITCH + akseg * 32;
                uint4 hv, lv;
                #pragma unroll
                for (int half = 0; half < 2; half++) {
                    const float* f = as + half * 8;
                    __nv_bfloat16 h0 = __float2bfloat16(f[0]), h1 = __float2bfloat16(f[1]);
                    __nv_bfloat16 h2 = __float2bfloat16(f[2]), h3 = __float2bfloat16(f[3]);
                    __nv_bfloat16 h4 = __float2bfloat16(f[4]), h5 = __float2bfloat16(f[5]);
                    __nv_bfloat16 h6 = __float2bfloat16(f[6]), h7 = __float2bfloat16(f[7]);
                    hv.x = pack_bf2(f[0], f[1]); hv.y = pack_bf2(f[2], f[3]);
                    hv.z = pack_bf2(f[4], f[5]); hv.w = pack_bf2(f[6], f[7]);
                    lv.x = pack_bf2(f[0]-__bfloat162float(h0), f[1]-__bfloat162float(h1));
                    lv.y = pack_bf2(f[2]-__bfloat162float(h2), f[3]-__bfloat162float(h3));
                    lv.z = pack_bf2(f[4]-__bfloat162float(h4), f[5]-__bfloat162float(h5));
                    lv.w = pack_bf2(f[6]-__bfloat162float(h6), f[7]-__bfloat162float(h7));
                    *(uint4*)(pa + half * 16) = hv;
                    *(uint4*)(pl + half * 16) = lv;
                }
                char* pbh = smem + SB_H + brow * PITCH + bseg * 64;
                char* pbl = smem + SB_L + brow * PITCH + bseg * 64;
                #pragma unroll
                for (int i = 0; i < 4; i++) {
                    *(uint4*)(pbh + i * 16) = bh4[i];
                    *(uint4*)(pbl + i * 16) = bl4[i];
                }
            }
            __syncthreads();

            if (c + 1 < NCH) {
                const int k0 = (c + 1) * CH;
                if (c + 1 < NCH - 1) {
                    const float4* ap4 = (const float4*)(aptr + k0 + akseg * 16);
                    #pragma unroll
                    for (int i = 0; i < 4; i++) {
                        float4 v = ap4[i];
                        as[4*i+0]=v.x; as[4*i+1]=v.y; as[4*i+2]=v.z; as[4*i+3]=v.w;
                    }
                } else {
                    #pragma unroll
                    for (int i = 0; i < 16; i++) {
                        int kg = k0 + akseg * 16 + i;
                        as[i] = (kg < GK) ? aptr[kg] : 0.f;
                    }
                }
                #pragma unroll
                for (int i = 0; i < 4; i++) {
                    bh4[i] = *(const uint4*)(bhp + k0 + i * 8);
                    bl4[i] = *(const uint4*)(blp + k0 + i * 8);
                }
            }

            const uint32_t aBaseH = sb + SA_H + (uint32_t)(wm * 32 * PITCH) + aOff;
            const uint32_t aBaseL = sb + SA_L + (uint32_t)(wm * 32 * PITCH) + aOff;
            const uint32_t bBaseH = sb + SB_H + (uint32_t)(wn * 32 * PITCH) + bOff;
            const uint32_t bBaseL = sb + SB_L + (uint32_t)(wn * 32 * PITCH) + bOff;

            #pragma unroll
            for (int ks = 0; ks < 4; ks++) {
                uint32_t ah[2][4], al[2][4], bhv[2][4], blv[2][4];
                #pragma unroll
                for (int mt = 0; mt < 2; mt++) {
                    ldm_x4(ah[mt], aBaseH + mt * 16 * PITCH + ks * 32);
                    ldm_x4(al[mt], aBaseL + mt * 16 * PITCH + ks * 32);
                }
                #pragma unroll
                for (int nh = 0; nh < 2; nh++) {
                    ldm_x4(bhv[nh], bBaseH + nh * 16 * PITCH + ks * 32);
                    ldm_x4(blv[nh], bBaseL + nh * 16 * PITCH + ks * 32);
                }
                #pragma unroll
                for (int mt = 0; mt < 2; mt++)
                    #pragma unroll
                    for (int nt = 0; nt < 4; nt++) {
                        const uint32_t* bhreg = &bhv[nt >> 1][(nt & 1) * 2];
                        const uint32_t* blreg = &blv[nt >> 1][(nt & 1) * 2];
                        mma16816(acc[mt][nt], ah[mt], bhreg);
                        mma16816(acc[mt][nt], al[mt], bhreg);
                        mma16816(acc[mt][nt], ah[mt], blreg);
                    }
            }
        }

        const int g = lane >> 2, t = lane & 3;
        #pragma unroll
        for (int mt = 0; mt < 2; mt++)
            #pragma unroll
            for (int nt = 0; nt < 4; nt++) {
                int row0 = bm + wm * 32 + mt * 16 + g;
                int col  = wn * 32 + nt * 8 + t * 2;
                *(float2*)&C[(size_t)row0 * 128 + col] =
                    make_float2(acc[mt][nt][0], acc[mt][nt][1]);
                *(float2*)&C[(size_t)(row0 + 8) * 128 + col] =
                    make_float2(acc[mt][nt][2], acc[mt][nt][3]);
            }
        return;
    }

    // ==================== attn branch ====================
    float* smem   = (float*)dyn_smem;
    float* h_s    = smem;                 // 128*132
    float* a_t    = h_s + 128 * HST;      // 4*132
    float* attn_s = a_t + 4 * HST;        // 2*128
    float* red    = attn_s + 256;         // 2*4

    const int idx = blockIdx.x - NGB;     // 0..511
    const int b   = idx >> 3;             // 0..63
    const int it  = idx & 7;              // 0..7  (16-row tile)
    const int tx  = tid & 127;
    const int ty  = tid >> 7;

    const float4* hb4 = (const float4*)(hidden + b * 16384);
    #pragma unroll 4
    for (int q = tid; q < 4096; q += 256) {
        int j  = q >> 5;
        int ds = q & 31;
        *(float4*)&h_s[j * HST + ds * 4] = hb4[q];
    }
    #pragma unroll
    for (int t = tid; t < 512; t += 256) {
        int k = t & 3, d = t >> 2;
        a_t[k * HST + d] = a[t];
    }
    __syncthreads();

    const int lane = tid & 31;
    const int w    = (tid >> 5) & 3;

    for (int ii = 0; ii < 8; ++ii) {
        const int i = it * 16 + ii * 2 + ty;

        const int e = adj[(b * 128 + i) * 128 + tx];
        const int k = (e > 0) ? (e - 1) : 0;

        const ulonglong2* hi2 = (const ulonglong2*)&h_s[i * HST];
        const ulonglong2* hj2 = (const ulonglong2*)&h_s[tx * HST];
        const ulonglong2* ar2 = (const ulonglong2*)&a_t[k * HST];

        // lrelu(p) = 0.6p + 0.4|p|  ->  alpha = 0.6*sum(p*w) + 0.4*sum(|p|*w)
        unsigned long long accA0 = 0ull, accA1 = 0ull;   // {0.f,0.f}
        unsigned long long accB0 = 0ull, accB1 = 0ull;
        #pragma unroll 8
        for (int dd = 0; dd < 32; ++dd) {
            ulonglong2 x = hi2[dd], y = hj2[dd], wv = ar2[dd];
            unsigned long long p0 = mul2(x.x, y.x);
            unsigned long long p1 = mul2(x.y, y.y);
            accA0 = fma2(p0, wv.x, accA0);
            accA1 = fma2(p1, wv.y, accA1);
            accB0 = fma2(p0 & 0x7FFFFFFF7FFFFFFFull, wv.x, accB0);
            accB1 = fma2(p1 & 0x7FFFFFFF7FFFFFFFull, wv.y, accB1);
        }
        float accA = pairsum(accA0) + pairsum(accA1);
        float accB = pairsum(accB0) + pairsum(accB1);
        float alpha = (e != 0) ? fmaf(0.6f, accA, 0.4f * accB) : NEG_INF_F;

        float m = alpha;
        #pragma unroll
        for (int o = 16; o; o >>= 1)
            m = fmaxf(m, __shfl_xor_sync(0xffffffffu, m, o));
        if (lane == 0) red[ty * 4 + w] = m;
        __syncthreads();
        m = fmaxf(fmaxf(red[ty * 4 + 0], red[ty * 4 + 1]),
                  fmaxf(red[ty * 4 + 2], red[ty * 4 + 3]));

        float ex = __expf(alpha - m);
        float s = ex;
        #pragma unroll
        for (int o = 16; o; o >>= 1)
            s += __shfl_xor_sync(0xffffffffu, s, o);
        __syncthreads();
        if (lane == 0) red[ty * 4 + w] = s;
        __syncthreads();
        s = (red[ty * 4 + 0] + red[ty * 4 + 1]) +
            (red[ty * 4 + 2] + red[ty * 4 + 3]);

        attn_s[ty * 128 + tx] = ex * (1.f / s);
        __syncthreads();

        const float4* at = (const float4*)&attn_s[ty * 128];
        float acc2 = 0.f;
        #pragma unroll 8
        for (int j4 = 0; j4 < 32; ++j4) {
            float4 av = at[j4];
            int j = j4 * 4;
            acc2 = fmaf(av.x, h_s[(j + 0) * HST + tx], acc2);
            acc2 = fmaf(av.y, h_s[(j + 1) * HST + tx], acc2);
            acc2 = fmaf(av.z, h_s[(j + 2) * HST + tx], acc2);
            acc2 = fmaf(av.w, h_s[(j + 3) * HST + tx], acc2);
        }
        out[(b * 128 + i) * 128 + tx] = acc2;
        __syncthreads();
    }
}

// ============================================================================
extern "C" void kernel_launch(void* const* d_in, const int* in_sizes, int n_in,
                              void* d_out, int out_size)
{
    const float* hidden   = (const float*)d_in[0];  // [64,128,128]
    const int*   adj      = (const int*)  d_in[1];  // [64,128,128]
    const float* a        = (const float*)d_in[2];  // [128,4]
    const float* A_attr   = (const float*)d_in[3];  // [64,128,1000]
    const float* attr_emb = (const float*)d_in[4];  // [1000,128]

    float* out       = (float*)d_out;
    float* out_attn  = out;                   // output    [64,128,128]
    float* out_attr  = out + 64 * 128 * 128;  // attr_sess [64,128,128]

    cudaFuncSetAttribute(fused_kernel,
                         cudaFuncAttributeMaxDynamicSharedMemorySize, SMEM_FUSED);

    bconv_kernel<<<512, 256>>>(attr_emb);
    fused_kernel<<<NGB + NAB, 256, SMEM_FUSED>>>(A_attr, out_attr,
                                                 hidden, adj, a, out_attn);
}

// round 11
// speedup vs baseline: 1.1185x; 1.1185x over previous
#include <cuda_runtime.h>
#include <cuda_bf16.h>
#include <cstdint>
#include <math.h>

#define NEG_INF_F   (-9.0e15f)

extern __shared__ char dyn_smem[];

// ============================================================================
// Helpers
// ============================================================================
__device__ __forceinline__ uint32_t s2u(const void* p) {
    uint32_t a;
    asm("{ .reg .u64 t; cvta.to.shared.u64 t, %1; cvt.u32.u64 %0, t; }"
        : "=r"(a) : "l"(p));
    return a;
}
__device__ __forceinline__ void ldm_x4(uint32_t* r, uint32_t addr) {
    asm volatile("ldmatrix.sync.aligned.m8n8.x4.shared.b16 {%0,%1,%2,%3}, [%4];"
                 : "=r"(r[0]), "=r"(r[1]), "=r"(r[2]), "=r"(r[3]) : "r"(addr));
}
__device__ __forceinline__ void mma16816(float* c, const uint32_t* a, const uint32_t* b) {
    asm volatile(
        "mma.sync.aligned.m16n8k16.row.col.f32.bf16.bf16.f32 "
        "{%0,%1,%2,%3}, {%4,%5,%6,%7}, {%8,%9}, {%0,%1,%2,%3};"
        : "+f"(c[0]), "+f"(c[1]), "+f"(c[2]), "+f"(c[3])
        : "r"(a[0]), "r"(a[1]), "r"(a[2]), "r"(a[3]), "r"(b[0]), "r"(b[1]));
}
__device__ __forceinline__ uint32_t pack_bf2(float a, float b) {
    __nv_bfloat162 t = __floats2bfloat162_rn(a, b);
    return *(uint32_t*)&t;
}
// Packed fp32 pair math (Blackwell f32x2; baseline sm_100+ PTX)
__device__ __forceinline__ unsigned long long mul2(unsigned long long a,
                                                   unsigned long long b) {
    unsigned long long d;
    asm("mul.rn.f32x2 %0, %1, %2;" : "=l"(d) : "l"(a), "l"(b));
    return d;
}
__device__ __forceinline__ unsigned long long fma2(unsigned long long a,
                                                   unsigned long long b,
                                                   unsigned long long c) {
    unsigned long long d;
    asm("fma.rn.f32x2 %0, %1, %2, %3;" : "=l"(d) : "l"(a), "l"(b), "l"(c));
    return d;
}
__device__ __forceinline__ float pairsum(unsigned long long v) {
    float2 f = *(float2*)&v;
    return f.x + f.y;
}

// ============================================================================
// Device scratch: B^T in bf16 hi/lo, K padded to 1024 (zeros). Bt[n][k]=B[k][n]
// ============================================================================
__device__ __nv_bfloat16 g_Bh[128 * 1024];
__device__ __nv_bfloat16 g_Bl[128 * 1024];

__global__ void __launch_bounds__(256) bconv_kernel(const float* __restrict__ B) {
    int idx = blockIdx.x * 256 + threadIdx.x;   // 131072
    int n = idx & 127;          // innermost -> coalesced reads of B[k][n]
    int k = idx >> 7;
    float v = (k < 1000) ? B[k * 128 + n] : 0.f;
    __nv_bfloat16 h = __float2bfloat16(v);
    g_Bh[n * 1024 + k] = h;
    g_Bl[n * 1024 + k] = __float2bfloat16(v - __bfloat162float(h));
}

// ============================================================================
// Kernel B: attr GEMM, warp-level bf16 mma.sync split (C = AhBh + AlBh + AhBl)
// C[8192,128] = A[8192,1000] @ B[1000,128]
// grid=128 (BM=64), 8 warps 2x4, warp tile 32x32, single-stage smem (R8 config).
// ============================================================================
#define GK     1000
#define CH     64
#define NCH    16
#define PITCH  144
#define SA_H   0
#define SA_L   (64 * PITCH)
#define SB_H   (2 * 64 * PITCH)
#define SB_L   (SB_H + 128 * PITCH)
#define SMEM_GEMM (SB_L + 128 * PITCH)      // 55296

__global__ void __launch_bounds__(256)
attr_gemm_mma(const float* __restrict__ A, float* __restrict__ C) {
    char* smem = dyn_smem;
    const uint32_t sb = s2u(smem);
    const int tid  = threadIdx.x;
    const int wid  = tid >> 5;
    const int lane = tid & 31;
    const int bm   = blockIdx.x * 64;
    const int wm = wid >> 2;
    const int wn = wid & 3;

    const uint32_t aOff = (uint32_t)((lane & 15) * PITCH + (lane >> 4) * 16);
    const uint32_t bOff = (uint32_t)(((((lane >> 4) & 1) << 3) + (lane & 7)) * PITCH
                                     + ((lane >> 3) & 1) * 16);

    const int arow = tid >> 2, akseg = tid & 3;
    const int brow = tid >> 1, bseg  = tid & 1;
    const float* aptr = A + (size_t)(bm + arow) * GK;
    const __nv_bfloat16* bhp = g_Bh + brow * 1024 + bseg * 32;
    const __nv_bfloat16* blp = g_Bl + brow * 1024 + bseg * 32;

    float  as[16];
    uint4  bh4[4], bl4[4];

    {
        const float4* ap4 = (const float4*)(aptr + akseg * 16);
        #pragma unroll
        for (int i = 0; i < 4; i++) {
            float4 v = ap4[i];
            as[4*i+0] = v.x; as[4*i+1] = v.y; as[4*i+2] = v.z; as[4*i+3] = v.w;
        }
        #pragma unroll
        for (int i = 0; i < 4; i++) {
            bh4[i] = *(const uint4*)(bhp + i * 8);
            bl4[i] = *(const uint4*)(blp + i * 8);
        }
    }

    float acc[2][4][4];
    #pragma unroll
    for (int mt = 0; mt < 2; mt++)
        #pragma unroll
        for (int nt = 0; nt < 4; nt++)
            #pragma unroll
            for (int q = 0; q < 4; q++) acc[mt][nt][q] = 0.f;

    #pragma unroll 1
    for (int c = 0; c < NCH; c++) {
        if (c > 0) __syncthreads();

        {
            char* pa = smem + SA_H + arow * PITCH + akseg * 32;
            char* pl = smem + SA_L + arow * PITCH + akseg * 32;
            uint4 hv, lv;
            #pragma unroll
            for (int half = 0; half < 2; half++) {
                const float* f = as + half * 8;
                __nv_bfloat16 h0 = __float2bfloat16(f[0]), h1 = __float2bfloat16(f[1]);
                __nv_bfloat16 h2 = __float2bfloat16(f[2]), h3 = __float2bfloat16(f[3]);
                __nv_bfloat16 h4 = __float2bfloat16(f[4]), h5 = __float2bfloat16(f[5]);
                __nv_bfloat16 h6 = __float2bfloat16(f[6]), h7 = __float2bfloat16(f[7]);
                hv.x = pack_bf2(f[0], f[1]); hv.y = pack_bf2(f[2], f[3]);
                hv.z = pack_bf2(f[4], f[5]); hv.w = pack_bf2(f[6], f[7]);
                lv.x = pack_bf2(f[0]-__bfloat162float(h0), f[1]-__bfloat162float(h1));
                lv.y = pack_bf2(f[2]-__bfloat162float(h2), f[3]-__bfloat162float(h3));
                lv.z = pack_bf2(f[4]-__bfloat162float(h4), f[5]-__bfloat162float(h5));
                lv.w = pack_bf2(f[6]-__bfloat162float(h6), f[7]-__bfloat162float(h7));
                *(uint4*)(pa + half * 16) = hv;
                *(uint4*)(pl + half * 16) = lv;
            }
            char* pbh = smem + SB_H + brow * PITCH + bseg * 64;
            char* pbl = smem + SB_L + brow * PITCH + bseg * 64;
            #pragma unroll
            for (int i = 0; i < 4; i++) {
                *(uint4*)(pbh + i * 16) = bh4[i];
                *(uint4*)(pbl + i * 16) = bl4[i];
            }
        }
        __syncthreads();

        if (c + 1 < NCH) {
            const int k0 = (c + 1) * CH;
            if (c + 1 < NCH - 1) {
                const float4* ap4 = (const float4*)(aptr + k0 + akseg * 16);
                #pragma unroll
                for (int i = 0; i < 4; i++) {
                    float4 v = ap4[i];
                    as[4*i+0]=v.x; as[4*i+1]=v.y; as[4*i+2]=v.z; as[4*i+3]=v.w;
                }
            } else {
                #pragma unroll
                for (int i = 0; i < 16; i++) {
                    int kg = k0 + akseg * 16 + i;
                    as[i] = (kg < GK) ? aptr[kg] : 0.f;
                }
            }
            #pragma unroll
            for (int i = 0; i < 4; i++) {
                bh4[i] = *(const uint4*)(bhp + k0 + i * 8);
                bl4[i] = *(const uint4*)(blp + k0 + i * 8);
            }
        }

        const uint32_t aBaseH = sb + SA_H + (uint32_t)(wm * 32 * PITCH) + aOff;
        const uint32_t aBaseL = sb + SA_L + (uint32_t)(wm * 32 * PITCH) + aOff;
        const uint32_t bBaseH = sb + SB_H + (uint32_t)(wn * 32 * PITCH) + bOff;
        const uint32_t bBaseL = sb + SB_L + (uint32_t)(wn * 32 * PITCH) + bOff;

        #pragma unroll
        for (int ks = 0; ks < 4; ks++) {
            uint32_t ah[2][4], al[2][4], bhv[2][4], blv[2][4];
            #pragma unroll
            for (int mt = 0; mt < 2; mt++) {
                ldm_x4(ah[mt], aBaseH + mt * 16 * PITCH + ks * 32);
                ldm_x4(al[mt], aBaseL + mt * 16 * PITCH + ks * 32);
            }
            #pragma unroll
            for (int nh = 0; nh < 2; nh++) {
                ldm_x4(bhv[nh], bBaseH + nh * 16 * PITCH + ks * 32);
                ldm_x4(blv[nh], bBaseL + nh * 16 * PITCH + ks * 32);
            }
            #pragma unroll
            for (int mt = 0; mt < 2; mt++)
                #pragma unroll
                for (int nt = 0; nt < 4; nt++) {
                    const uint32_t* bhreg = &bhv[nt >> 1][(nt & 1) * 2];
                    const uint32_t* blreg = &blv[nt >> 1][(nt & 1) * 2];
                    mma16816(acc[mt][nt], ah[mt], bhreg);
                    mma16816(acc[mt][nt], al[mt], bhreg);
                    mma16816(acc[mt][nt], ah[mt], blreg);
                }
        }
    }

    const int g = lane >> 2, t = lane & 3;
    #pragma unroll
    for (int mt = 0; mt < 2; mt++)
        #pragma unroll
        for (int nt = 0; nt < 4; nt++) {
            int row0 = bm + wm * 32 + mt * 16 + g;
            int col  = wn * 32 + nt * 8 + t * 2;
            *(float2*)&C[(size_t)row0 * 128 + col] =
                make_float2(acc[mt][nt][0], acc[mt][nt][1]);
            *(float2*)&C[(size_t)(row0 + 8) * 128 + col] =
                make_float2(acc[mt][nt][2], acc[mt][nt][3]);
        }
}

// ============================================================================
// Kernel A: masked edge-type attention, f32x2 score loop.
// grid = 64 batches x 8 i-tiles (16 rows each), 256 threads as (128 j/d, 2 i).
// h_s row-major [j][d], stride 132 (conflict-free; R9 proved swizzle unneeded).
// lrelu(p) = 0.6p + 0.4|p|, |p| = |h_i||h_j| handled via packed AND.
// ============================================================================
#define HST 132
#define SMEM_ATTN ((128 * HST + 4 * HST + 256 + 8) * 4)   // 70752

__global__ void __launch_bounds__(256) attn_kernel(
    const float* __restrict__ hidden,   // [64,128,128]
    const int*   __restrict__ adj,      // [64,128,128]
    const float* __restrict__ a,        // [128,4]
    float*       __restrict__ out)      // [64,128,128]
{
    float* smem   = (float*)dyn_smem;
    float* h_s    = smem;                 // 128*132
    float* a_t    = h_s + 128 * HST;      // 4*132
    float* attn_s = a_t + 4 * HST;        // 2*128
    float* red    = attn_s + 256;         // 2*4

    const int tid = threadIdx.x;
    const int b   = blockIdx.x;
    const int it  = blockIdx.y;           // 0..7
    const int tx  = tid & 127;
    const int ty  = tid >> 7;

    const float4* hb4 = (const float4*)(hidden + b * 16384);
    #pragma unroll 4
    for (int q = tid; q < 4096; q += 256) {
        int j  = q >> 5;
        int ds = q & 31;
        *(float4*)&h_s[j * HST + ds * 4] = hb4[q];
    }
    #pragma unroll
    for (int t = tid; t < 512; t += 256) {
        int k = t & 3, d = t >> 2;
        a_t[k * HST + d] = a[t];
    }
    __syncthreads();

    const int lane = tid & 31;
    const int w    = (tid >> 5) & 3;

    for (int ii = 0; ii < 8; ++ii) {
        const int i = it * 16 + ii * 2 + ty;

        const int e = adj[(b * 128 + i) * 128 + tx];
        const int k = (e > 0) ? (e - 1) : 0;

        const ulonglong2* hi2 = (const ulonglong2*)&h_s[i * HST];
        const ulonglong2* hj2 = (const ulonglong2*)&h_s[tx * HST];
        const ulonglong2* ar2 = (const ulonglong2*)&a_t[k * HST];

        unsigned long long accA0 = 0ull, accA1 = 0ull;   // {0.f,0.f}
        unsigned long long accB0 = 0ull, accB1 = 0ull;
        #pragma unroll 8
        for (int dd = 0; dd < 32; ++dd) {
            ulonglong2 x = hi2[dd], y = hj2[dd], wv = ar2[dd];
            unsigned long long p0 = mul2(x.x, y.x);
            unsigned long long p1 = mul2(x.y, y.y);
            accA0 = fma2(p0, wv.x, accA0);
            accA1 = fma2(p1, wv.y, accA1);
            accB0 = fma2(p0 & 0x7FFFFFFF7FFFFFFFull, wv.x, accB0);
            accB1 = fma2(p1 & 0x7FFFFFFF7FFFFFFFull, wv.y, accB1);
        }
        float accA = pairsum(accA0) + pairsum(accA1);
        float accB = pairsum(accB0) + pairsum(accB1);
        float alpha = (e != 0) ? fmaf(0.6f, accA, 0.4f * accB) : NEG_INF_F;

        float m = alpha;
        #pragma unroll
        for (int o = 16; o; o >>= 1)
            m = fmaxf(m, __shfl_xor_sync(0xffffffffu, m, o));
        if (lane == 0) red[ty * 4 + w] = m;
        __syncthreads();
        m = fmaxf(fmaxf(red[ty * 4 + 0], red[ty * 4 + 1]),
                  fmaxf(red[ty * 4 + 2], red[ty * 4 + 3]));

        float ex = __expf(alpha - m);
        float s = ex;
        #pragma unroll
        for (int o = 16; o; o >>= 1)
            s += __shfl_xor_sync(0xffffffffu, s, o);
        __syncthreads();
        if (lane == 0) red[ty * 4 + w] = s;
        __syncthreads();
        s = (red[ty * 4 + 0] + red[ty * 4 + 1]) +
            (red[ty * 4 + 2] + red[ty * 4 + 3]);

        attn_s[ty * 128 + tx] = ex * (1.f / s);
        __syncthreads();

        const float4* at = (const float4*)&attn_s[ty * 128];
        float acc2 = 0.f;
        #pragma unroll 8
        for (int j4 = 0; j4 < 32; ++j4) {
            float4 av = at[j4];
            int j = j4 * 4;
            acc2 = fmaf(av.x, h_s[(j + 0) * HST + tx], acc2);
            acc2 = fmaf(av.y, h_s[(j + 1) * HST + tx], acc2);
            acc2 = fmaf(av.z, h_s[(j + 2) * HST + tx], acc2);
            acc2 = fmaf(av.w, h_s[(j + 3) * HST + tx], acc2);
        }
        out[(b * 128 + i) * 128 + tx] = acc2;
        __syncthreads();
    }
}

// ============================================================================
extern "C" void kernel_launch(void* const* d_in, const int* in_sizes, int n_in,
                              void* d_out, int out_size)
{
    const float* hidden   = (const float*)d_in[0];  // [64,128,128]
    const int*   adj      = (const int*)  d_in[1];  // [64,128,128]
    const float* a        = (const float*)d_in[2];  // [128,4]
    const float* A_attr   = (const float*)d_in[3];  // [64,128,1000]
    const float* attr_emb = (const float*)d_in[4];  // [1000,128]

    float* out       = (float*)d_out;
    float* out_attn  = out;                   // output    [64,128,128]
    float* out_attr  = out + 64 * 128 * 128;  // attr_sess [64,128,128]

    cudaFuncSetAttribute(attn_kernel,
                         cudaFuncAttributeMaxDynamicSharedMemorySize, SMEM_ATTN);
    cudaFuncSetAttribute(attr_gemm_mma,
                         cudaFuncAttributeMaxDynamicSharedMemorySize, SMEM_GEMM);

    attn_kernel<<<dim3(64, 8), 256, SMEM_ATTN>>>(hidden, adj, a, out_attn);
    bconv_kernel<<<512, 256>>>(attr_emb);
    attr_gemm_mma<<<128, 256, SMEM_GEMM>>>(A_attr, out_attr);
}

// round 12
// speedup vs baseline: 1.1529x; 1.0308x over previous
#include <cuda_runtime.h>
#include <cuda_bf16.h>
#include <cstdint>
#include <math.h>

#define NEG_INF_F   (-9.0e15f)

extern __shared__ char dyn_smem[];

// ============================================================================
// Helpers
// ============================================================================
__device__ __forceinline__ uint32_t s2u(const void* p) {
    uint32_t a;
    asm("{ .reg .u64 t; cvta.to.shared.u64 t, %1; cvt.u32.u64 %0, t; }"
        : "=r"(a) : "l"(p));
    return a;
}
__device__ __forceinline__ void ldm_x4(uint32_t* r, uint32_t addr) {
    asm volatile("ldmatrix.sync.aligned.m8n8.x4.shared.b16 {%0,%1,%2,%3}, [%4];"
                 : "=r"(r[0]), "=r"(r[1]), "=r"(r[2]), "=r"(r[3]) : "r"(addr));
}
__device__ __forceinline__ void mma16816(float* c, const uint32_t* a, const uint32_t* b) {
    asm volatile(
        "mma.sync.aligned.m16n8k16.row.col.f32.bf16.bf16.f32 "
        "{%0,%1,%2,%3}, {%4,%5,%6,%7}, {%8,%9}, {%0,%1,%2,%3};"
        : "+f"(c[0]), "+f"(c[1]), "+f"(c[2]), "+f"(c[3])
        : "r"(a[0]), "r"(a[1]), "r"(a[2]), "r"(a[3]), "r"(b[0]), "r"(b[1]));
}
__device__ __forceinline__ uint32_t pack_bf2(float a, float b) {
    __nv_bfloat162 t = __floats2bfloat162_rn(a, b);
    return *(uint32_t*)&t;
}
// Packed fp32 pair math (Blackwell f32x2)
__device__ __forceinline__ unsigned long long mul2(unsigned long long a,
                                                   unsigned long long b) {
    unsigned long long d;
    asm("mul.rn.f32x2 %0, %1, %2;" : "=l"(d) : "l"(a), "l"(b));
    return d;
}
__device__ __forceinline__ unsigned long long fma2(unsigned long long a,
                                                   unsigned long long b,
                                                   unsigned long long c) {
    unsigned long long d;
    asm("fma.rn.f32x2 %0, %1, %2, %3;" : "=l"(d) : "l"(a), "l"(b), "l"(c));
    return d;
}
__device__ __forceinline__ float pairsum(unsigned long long v) {
    float2 f = *(float2*)&v;
    return f.x + f.y;
}

// ============================================================================
// Device scratch: B^T in bf16 hi/lo, K padded to 1024 (zeros). Bt[n][k]=B[k][n]
// ============================================================================
__device__ __nv_bfloat16 g_Bh[128 * 1024];
__device__ __nv_bfloat16 g_Bl[128 * 1024];

__global__ void __launch_bounds__(256) bconv_kernel(const float* __restrict__ B) {
    int idx = blockIdx.x * 256 + threadIdx.x;   // 131072
    int n = idx & 127;
    int k = idx >> 7;
    float v = (k < 1000) ? B[k * 128 + n] : 0.f;
    __nv_bfloat16 h = __float2bfloat16(v);
    g_Bh[n * 1024 + k] = h;
    g_Bl[n * 1024 + k] = __float2bfloat16(v - __bfloat162float(h));
}

__global__ void noop_kernel() {}   // pads launch count so ncu captures the GEMM

// ============================================================================
// Kernel B: attr GEMM, warp-level bf16 mma.sync split (C = AhBh + AlBh + AhBl)
// (unchanged from R11)
// ============================================================================
#define GK     1000
#define CH     64
#define NCH    16
#define PITCH  144
#define SA_H   0
#define SA_L   (64 * PITCH)
#define SB_H   (2 * 64 * PITCH)
#define SB_L   (SB_H + 128 * PITCH)
#define SMEM_GEMM (SB_L + 128 * PITCH)      // 55296

__global__ void __launch_bounds__(256)
attr_gemm_mma(const float* __restrict__ A, float* __restrict__ C) {
    char* smem = dyn_smem;
    const uint32_t sb = s2u(smem);
    const int tid  = threadIdx.x;
    const int wid  = tid >> 5;
    const int lane = tid & 31;
    const int bm   = blockIdx.x * 64;
    const int wm = wid >> 2;
    const int wn = wid & 3;

    const uint32_t aOff = (uint32_t)((lane & 15) * PITCH + (lane >> 4) * 16);
    const uint32_t bOff = (uint32_t)(((((lane >> 4) & 1) << 3) + (lane & 7)) * PITCH
                                     + ((lane >> 3) & 1) * 16);

    const int arow = tid >> 2, akseg = tid & 3;
    const int brow = tid >> 1, bseg  = tid & 1;
    const float* aptr = A + (size_t)(bm + arow) * GK;
    const __nv_bfloat16* bhp = g_Bh + brow * 1024 + bseg * 32;
    const __nv_bfloat16* blp = g_Bl + brow * 1024 + bseg * 32;

    float  as[16];
    uint4  bh4[4], bl4[4];

    {
        const float4* ap4 = (const float4*)(aptr + akseg * 16);
        #pragma unroll
        for (int i = 0; i < 4; i++) {
            float4 v = ap4[i];
            as[4*i+0] = v.x; as[4*i+1] = v.y; as[4*i+2] = v.z; as[4*i+3] = v.w;
        }
        #pragma unroll
        for (int i = 0; i < 4; i++) {
            bh4[i] = *(const uint4*)(bhp + i * 8);
            bl4[i] = *(const uint4*)(blp + i * 8);
        }
    }

    float acc[2][4][4];
    #pragma unroll
    for (int mt = 0; mt < 2; mt++)
        #pragma unroll
        for (int nt = 0; nt < 4; nt++)
            #pragma unroll
            for (int q = 0; q < 4; q++) acc[mt][nt][q] = 0.f;

    #pragma unroll 1
    for (int c = 0; c < NCH; c++) {
        if (c > 0) __syncthreads();

        {
            char* pa = smem + SA_H + arow * PITCH + akseg * 32;
            char* pl = smem + SA_L + arow * PITCH + akseg * 32;
            uint4 hv, lv;
            #pragma unroll
            for (int half = 0; half < 2; half++) {
                const float* f = as + half * 8;
                __nv_bfloat16 h0 = __float2bfloat16(f[0]), h1 = __float2bfloat16(f[1]);
                __nv_bfloat16 h2 = __float2bfloat16(f[2]), h3 = __float2bfloat16(f[3]);
                __nv_bfloat16 h4 = __float2bfloat16(f[4]), h5 = __float2bfloat16(f[5]);
                __nv_bfloat16 h6 = __float2bfloat16(f[6]), h7 = __float2bfloat16(f[7]);
                hv.x = pack_bf2(f[0], f[1]); hv.y = pack_bf2(f[2], f[3]);
                hv.z = pack_bf2(f[4], f[5]); hv.w = pack_bf2(f[6], f[7]);
                lv.x = pack_bf2(f[0]-__bfloat162float(h0), f[1]-__bfloat162float(h1));
                lv.y = pack_bf2(f[2]-__bfloat162float(h2), f[3]-__bfloat162float(h3));
                lv.z = pack_bf2(f[4]-__bfloat162float(h4), f[5]-__bfloat162float(h5));
                lv.w = pack_bf2(f[6]-__bfloat162float(h6), f[7]-__bfloat162float(h7));
                *(uint4*)(pa + half * 16) = hv;
                *(uint4*)(pl + half * 16) = lv;
            }
            char* pbh = smem + SB_H + brow * PITCH + bseg * 64;
            char* pbl = smem + SB_L + brow * PITCH + bseg * 64;
            #pragma unroll
            for (int i = 0; i < 4; i++) {
                *(uint4*)(pbh + i * 16) = bh4[i];
                *(uint4*)(pbl + i * 16) = bl4[i];
            }
        }
        __syncthreads();

        if (c + 1 < NCH) {
            const int k0 = (c + 1) * CH;
            if (c + 1 < NCH - 1) {
                const float4* ap4 = (const float4*)(aptr + k0 + akseg * 16);
                #pragma unroll
                for (int i = 0; i < 4; i++) {
                    float4 v = ap4[i];
                    as[4*i+0]=v.x; as[4*i+1]=v.y; as[4*i+2]=v.z; as[4*i+3]=v.w;
                }
            } else {
                #pragma unroll
                for (int i = 0; i < 16; i++) {
                    int kg = k0 + akseg * 16 + i;
                    as[i] = (kg < GK) ? aptr[kg] : 0.f;
                }
            }
            #pragma unroll
            for (int i = 0; i < 4; i++) {
                bh4[i] = *(const uint4*)(bhp + k0 + i * 8);
                bl4[i] = *(const uint4*)(blp + k0 + i * 8);
            }
        }

        const uint32_t aBaseH = sb + SA_H + (uint32_t)(wm * 32 * PITCH) + aOff;
        const uint32_t aBaseL = sb + SA_L + (uint32_t)(wm * 32 * PITCH) + aOff;
        const uint32_t bBaseH = sb + SB_H + (uint32_t)(wn * 32 * PITCH) + bOff;
        const uint32_t bBaseL = sb + SB_L + (uint32_t)(wn * 32 * PITCH) + bOff;

        #pragma unroll
        for (int ks = 0; ks < 4; ks++) {
            uint32_t ah[2][4], al[2][4], bhv[2][4], blv[2][4];
            #pragma unroll
            for (int mt = 0; mt < 2; mt++) {
                ldm_x4(ah[mt], aBaseH + mt * 16 * PITCH + ks * 32);
                ldm_x4(al[mt], aBaseL + mt * 16 * PITCH + ks * 32);
            }
            #pragma unroll
            for (int nh = 0; nh < 2; nh++) {
                ldm_x4(bhv[nh], bBaseH + nh * 16 * PITCH + ks * 32);
                ldm_x4(blv[nh], bBaseL + nh * 16 * PITCH + ks * 32);
            }
            #pragma unroll
            for (int mt = 0; mt < 2; mt++)
                #pragma unroll
                for (int nt = 0; nt < 4; nt++) {
                    const uint32_t* bhreg = &bhv[nt >> 1][(nt & 1) * 2];
                    const uint32_t* blreg = &blv[nt >> 1][(nt & 1) * 2];
                    mma16816(acc[mt][nt], ah[mt], bhreg);
                    mma16816(acc[mt][nt], al[mt], bhreg);
                    mma16816(acc[mt][nt], ah[mt], blreg);
                }
        }
    }

    const int g = lane >> 2, t = lane & 3;
    #pragma unroll
    for (int mt = 0; mt < 2; mt++)
        #pragma unroll
        for (int nt = 0; nt < 4; nt++) {
            int row0 = bm + wm * 32 + mt * 16 + g;
            int col  = wn * 32 + nt * 8 + t * 2;
            *(float2*)&C[(size_t)row0 * 128 + col] =
                make_float2(acc[mt][nt][0], acc[mt][nt][1]);
            *(float2*)&C[(size_t)(row0 + 8) * 128 + col] =
                make_float2(acc[mt][nt][2], acc[mt][nt][3]);
        }
}

// ============================================================================
// Kernel A: masked edge-type attention — d-split register caching.
// Threads: tx = tid&127 (j in score / d in out), th = tid>>7 (d-half / j-half).
// Each thread keeps h_{j=tx}[th*64 .. th*64+63] in registers -> score loop
// LDS is only broadcast h_i + 4-way-dedup a rows (~32 wf vs 192 per warp-i).
// grid = (64 batches, 8 i-tiles of 16); one i per inner iteration.
// ============================================================================
#define HST 132
#define SM_HS    0
#define SM_AT    (128 * HST)                 // +4*HST
#define SM_ATTN  (SM_AT + 4 * HST)           // +128
#define SM_RED   (SM_ATTN + 128)             // +8
#define SM_PART  (SM_RED + 8)                // float2[2][128] -> 512 floats
#define SM_OUTP  (SM_PART + 512)             // float [2][128] -> 256 floats
#define SMEM_ATTN ((SM_OUTP + 256) * 4)      // bytes

__global__ void __launch_bounds__(256, 2) attn_kernel(
    const float* __restrict__ hidden,   // [64,128,128]
    const int*   __restrict__ adj,      // [64,128,128]
    const float* __restrict__ a,        // [128,4]
    float*       __restrict__ out)      // [64,128,128]
{
    float* smem   = (float*)dyn_smem;
    float*  h_s    = smem + SM_HS;
    float*  a_t    = smem + SM_AT;
    float*  attn_s = smem + SM_ATTN;
    float*  red    = smem + SM_RED;
    float2* part   = (float2*)(smem + SM_PART);
    float*  outp   = smem + SM_OUTP;

    const int tid = threadIdx.x;
    const int b   = blockIdx.x;
    const int it  = blockIdx.y;           // 0..7
    const int tx  = tid & 127;
    const int th  = tid >> 7;             // 0..1

    const float4* hb4 = (const float4*)(hidden + b * 16384);
    #pragma unroll 4
    for (int q = tid; q < 4096; q += 256) {
        int j  = q >> 5;
        int ds = q & 31;
        *(float4*)&h_s[j * HST + ds * 4] = hb4[q];
    }
    #pragma unroll
    for (int t = tid; t < 512; t += 256) {
        int k = t & 3, d = t >> 2;
        a_t[k * HST + d] = a[t];
    }
    __syncthreads();

    // register cache: own half-row of h_j (j = tx, d in [th*64, th*64+64))
    ulonglong2 hj[16];
    {
        const ulonglong2* hrow = (const ulonglong2*)&h_s[tx * HST + th * 64];
        #pragma unroll
        for (int c = 0; c < 16; c++) hj[c] = hrow[c];
    }

    const int lane = tid & 31;
    const int w    = (tid >> 5) & 3;
    const unsigned long long ABSM = 0x7FFFFFFF7FFFFFFFull;

    for (int ii = 0; ii < 16; ++ii) {
        const int i = it * 16 + ii;

        const int e = adj[(b * 128 + i) * 128 + tx];
        const int k = (e > 0) ? (e - 1) : 0;

        const ulonglong2* hi2 = (const ulonglong2*)&h_s[i * HST + th * 64];
        const ulonglong2* ar2 = (const ulonglong2*)&a_t[k * HST + th * 64];

        unsigned long long accA0 = 0ull, accA1 = 0ull;
        unsigned long long accB0 = 0ull, accB1 = 0ull;
        #pragma unroll
        for (int c = 0; c < 16; ++c) {
            ulonglong2 x = hi2[c], wv = ar2[c];
            unsigned long long p0 = mul2(x.x, hj[c].x);
            unsigned long long p1 = mul2(x.y, hj[c].y);
            accA0 = fma2(p0, wv.x, accA0);
            accA1 = fma2(p1, wv.y, accA1);
            accB0 = fma2(p0 & ABSM, wv.x, accB0);
            accB1 = fma2(p1 & ABSM, wv.y, accB1);
        }
        part[th * 128 + tx] = make_float2(pairsum(accA0) + pairsum(accA1),
                                          pairsum(accB0) + pairsum(accB1));
        __syncthreads();

        float2 q0 = part[tx], q1 = part[128 + tx];
        float alpha = (e != 0)
            ? fmaf(0.6f, q0.x + q1.x, 0.4f * (q0.y + q1.y))
            : NEG_INF_F;

        // softmax over j (each th group redundantly computes; red indexed by th)
        float m = alpha;
        #pragma unroll
        for (int o = 16; o; o >>= 1)
            m = fmaxf(m, __shfl_xor_sync(0xffffffffu, m, o));
        if (lane == 0) red[th * 4 + w] = m;
        __syncthreads();
        m = fmaxf(fmaxf(red[th * 4 + 0], red[th * 4 + 1]),
                  fmaxf(red[th * 4 + 2], red[th * 4 + 3]));

        float ex = __expf(alpha - m);
        float s = ex;
        #pragma unroll
        for (int o = 16; o; o >>= 1)
            s += __shfl_xor_sync(0xffffffffu, s, o);
        __syncthreads();
        if (lane == 0) red[th * 4 + w] = s;
        __syncthreads();
        s = (red[th * 4 + 0] + red[th * 4 + 1]) +
            (red[th * 4 + 2] + red[th * 4 + 3]);

        if (th == 0) attn_s[tx] = ex * (1.f / s);
        __syncthreads();

        // out[i][d=tx] = sum_j attn[j] h[j][tx]; th splits the j-range
        const float4* at = (const float4*)&attn_s[th * 64];
        float acc2 = 0.f;
        #pragma unroll
        for (int j4 = 0; j4 < 16; ++j4) {
            float4 av = at[j4];
            int j = th * 64 + j4 * 4;
            acc2 = fmaf(av.x, h_s[(j + 0) * HST + tx], acc2);
            acc2 = fmaf(av.y, h_s[(j + 1) * HST + tx], acc2);
            acc2 = fmaf(av.z, h_s[(j + 2) * HST + tx], acc2);
            acc2 = fmaf(av.w, h_s[(j + 3) * HST + tx], acc2);
        }
        outp[th * 128 + tx] = acc2;
        __syncthreads();
        if (th == 0)
            out[(b * 128 + i) * 128 + tx] = outp[tx] + outp[128 + tx];
    }
}

// ============================================================================
extern "C" void kernel_launch(void* const* d_in, const int* in_sizes, int n_in,
                              void* d_out, int out_size)
{
    const float* hidden   = (const float*)d_in[0];  // [64,128,128]
    const int*   adj      = (const int*)  d_in[1];  // [64,128,128]
    const float* a        = (const float*)d_in[2];  // [128,4]
    const float* A_attr   = (const float*)d_in[3];  // [64,128,1000]
    const float* attr_emb = (const float*)d_in[4];  // [1000,128]

    float* out       = (float*)d_out;
    float* out_attn  = out;                   // output    [64,128,128]
    float* out_attr  = out + 64 * 128 * 128;  // attr_sess [64,128,128]

    cudaFuncSetAttribute(attn_kernel,
                         cudaFuncAttributeMaxDynamicSharedMemorySize, SMEM_ATTN);
    cudaFuncSetAttribute(attr_gemm_mma,
                         cudaFuncAttributeMaxDynamicSharedMemorySize, SMEM_GEMM);

    // ncu captures launch #3 of a replay -> gemm this time.
    bconv_kernel<<<512, 256>>>(attr_emb);
    attn_kernel<<<dim3(64, 8), 256, SMEM_ATTN>>>(hidden, adj, a, out_attn);
    attr_gemm_mma<<<128, 256, SMEM_GEMM>>>(A_attr, out_attr);
    noop_kernel<<<1, 32>>>();
}

// round 13
// speedup vs baseline: 1.6832x; 1.4599x over previous
#include <cuda_runtime.h>
#include <cuda_bf16.h>
#include <cstdint>
#include <math.h>

#define NEG_INF_F   (-9.0e15f)

extern __shared__ char dyn_smem[];

// ============================================================================
// Helpers (all battle-tested in prior rounds)
// ============================================================================
__device__ __forceinline__ uint32_t s2u(const void* p) {
    uint32_t a;
    asm("{ .reg .u64 t; cvta.to.shared.u64 t, %1; cvt.u32.u64 %0, t; }"
        : "=r"(a) : "l"(p));
    return a;
}
__device__ __forceinline__ void ldm_x4(uint32_t* r, uint32_t addr) {
    asm volatile("ldmatrix.sync.aligned.m8n8.x4.shared.b16 {%0,%1,%2,%3}, [%4];"
                 : "=r"(r[0]), "=r"(r[1]), "=r"(r[2]), "=r"(r[3]) : "r"(addr));
}
__device__ __forceinline__ void mma16816(float* c, const uint32_t* a, const uint32_t* b) {
    asm volatile(
        "mma.sync.aligned.m16n8k16.row.col.f32.bf16.bf16.f32 "
        "{%0,%1,%2,%3}, {%4,%5,%6,%7}, {%8,%9}, {%0,%1,%2,%3};"
        : "+f"(c[0]), "+f"(c[1]), "+f"(c[2]), "+f"(c[3])
        : "r"(a[0]), "r"(a[1]), "r"(a[2]), "r"(a[3]), "r"(b[0]), "r"(b[1]));
}
__device__ __forceinline__ uint32_t pack_bf2(float a, float b) {
    __nv_bfloat162 t = __floats2bfloat162_rn(a, b);
    return *(uint32_t*)&t;
}

// ============================================================================
// Device scratch: B^T in bf16 hi/lo, K padded to 1024 (zeros). Bt[n][k]=B[k][n]
// ============================================================================
__device__ __nv_bfloat16 g_Bh[128 * 1024];
__device__ __nv_bfloat16 g_Bl[128 * 1024];

__global__ void __launch_bounds__(256) bconv_kernel(const float* __restrict__ B) {
    int idx = blockIdx.x * 256 + threadIdx.x;   // 131072
    int n = idx & 127;
    int k = idx >> 7;
    float v = (k < 1000) ? B[k * 128 + n] : 0.f;
    __nv_bfloat16 h = __float2bfloat16(v);
    g_Bh[n * 1024 + k] = h;
    g_Bl[n * 1024 + k] = __float2bfloat16(v - __bfloat162float(h));
}

// ============================================================================
// Kernel B: attr GEMM, warp-level bf16 mma.sync split (unchanged, proven)
// ============================================================================
#define GK     1000
#define CH     64
#define NCH    16
#define PITCH  144
#define SA_H   0
#define SA_L   (64 * PITCH)
#define SB_H   (2 * 64 * PITCH)
#define SB_L   (SB_H + 128 * PITCH)
#define SMEM_GEMM (SB_L + 128 * PITCH)      // 55296

__global__ void __launch_bounds__(256)
attr_gemm_mma(const float* __restrict__ A, float* __restrict__ C) {
    char* smem = dyn_smem;
    const uint32_t sb = s2u(smem);
    const int tid  = threadIdx.x;
    const int wid  = tid >> 5;
    const int lane = tid & 31;
    const int bm   = blockIdx.x * 64;
    const int wm = wid >> 2;
    const int wn = wid & 3;

    const uint32_t aOff = (uint32_t)((lane & 15) * PITCH + (lane >> 4) * 16);
    const uint32_t bOff = (uint32_t)(((((lane >> 4) & 1) << 3) + (lane & 7)) * PITCH
                                     + ((lane >> 3) & 1) * 16);

    const int arow = tid >> 2, akseg = tid & 3;
    const int brow = tid >> 1, bseg  = tid & 1;
    const float* aptr = A + (size_t)(bm + arow) * GK;
    const __nv_bfloat16* bhp = g_Bh + brow * 1024 + bseg * 32;
    const __nv_bfloat16* blp = g_Bl + brow * 1024 + bseg * 32;

    float  as[16];
    uint4  bh4[4], bl4[4];

    {
        const float4* ap4 = (const float4*)(aptr + akseg * 16);
        #pragma unroll
        for (int i = 0; i < 4; i++) {
            float4 v = ap4[i];
            as[4*i+0] = v.x; as[4*i+1] = v.y; as[4*i+2] = v.z; as[4*i+3] = v.w;
        }
        #pragma unroll
        for (int i = 0; i < 4; i++) {
            bh4[i] = *(const uint4*)(bhp + i * 8);
            bl4[i] = *(const uint4*)(blp + i * 8);
        }
    }

    float acc[2][4][4];
    #pragma unroll
    for (int mt = 0; mt < 2; mt++)
        #pragma unroll
        for (int nt = 0; nt < 4; nt++)
            #pragma unroll
            for (int q = 0; q < 4; q++) acc[mt][nt][q] = 0.f;

    #pragma unroll 1
    for (int c = 0; c < NCH; c++) {
        if (c > 0) __syncthreads();

        {
            char* pa = smem + SA_H + arow * PITCH + akseg * 32;
            char* pl = smem + SA_L + arow * PITCH + akseg * 32;
            uint4 hv, lv;
            #pragma unroll
            for (int half = 0; half < 2; half++) {
                const float* f = as + half * 8;
                __nv_bfloat16 h0 = __float2bfloat16(f[0]), h1 = __float2bfloat16(f[1]);
                __nv_bfloat16 h2 = __float2bfloat16(f[2]), h3 = __float2bfloat16(f[3]);
                __nv_bfloat16 h4 = __float2bfloat16(f[4]), h5 = __float2bfloat16(f[5]);
                __nv_bfloat16 h6 = __float2bfloat16(f[6]), h7 = __float2bfloat16(f[7]);
                hv.x = pack_bf2(f[0], f[1]); hv.y = pack_bf2(f[2], f[3]);
                hv.z = pack_bf2(f[4], f[5]); hv.w = pack_bf2(f[6], f[7]);
                lv.x = pack_bf2(f[0]-__bfloat162float(h0), f[1]-__bfloat162float(h1));
                lv.y = pack_bf2(f[2]-__bfloat162float(h2), f[3]-__bfloat162float(h3));
                lv.z = pack_bf2(f[4]-__bfloat162float(h4), f[5]-__bfloat162float(h5));
                lv.w = pack_bf2(f[6]-__bfloat162float(h6), f[7]-__bfloat162float(h7));
                *(uint4*)(pa + half * 16) = hv;
                *(uint4*)(pl + half * 16) = lv;
            }
            char* pbh = smem + SB_H + brow * PITCH + bseg * 64;
            char* pbl = smem + SB_L + brow * PITCH + bseg * 64;
            #pragma unroll
            for (int i = 0; i < 4; i++) {
                *(uint4*)(pbh + i * 16) = bh4[i];
                *(uint4*)(pbl + i * 16) = bl4[i];
            }
        }
        __syncthreads();

        if (c + 1 < NCH) {
            const int k0 = (c + 1) * CH;
            if (c + 1 < NCH - 1) {
                const float4* ap4 = (const float4*)(aptr + k0 + akseg * 16);
                #pragma unroll
                for (int i = 0; i < 4; i++) {
                    float4 v = ap4[i];
                    as[4*i+0]=v.x; as[4*i+1]=v.y; as[4*i+2]=v.z; as[4*i+3]=v.w;
                }
            } else {
                #pragma unroll
                for (int i = 0; i < 16; i++) {
                    int kg = k0 + akseg * 16 + i;
                    as[i] = (kg < GK) ? aptr[kg] : 0.f;
                }
            }
            #pragma unroll
            for (int i = 0; i < 4; i++) {
                bh4[i] = *(const uint4*)(bhp + k0 + i * 8);
                bl4[i] = *(const uint4*)(blp + k0 + i * 8);
            }
        }

        const uint32_t aBaseH = sb + SA_H + (uint32_t)(wm * 32 * PITCH) + aOff;
        const uint32_t aBaseL = sb + SA_L + (uint32_t)(wm * 32 * PITCH) + aOff;
        const uint32_t bBaseH = sb + SB_H + (uint32_t)(wn * 32 * PITCH) + bOff;
        const uint32_t bBaseL = sb + SB_L + (uint32_t)(wn * 32 * PITCH) + bOff;

        #pragma unroll
        for (int ks = 0; ks < 4; ks++) {
            uint32_t ah[2][4], al[2][4], bhv[2][4], blv[2][4];
            #pragma unroll
            for (int mt = 0; mt < 2; mt++) {
                ldm_x4(ah[mt], aBaseH + mt * 16 * PITCH + ks * 32);
                ldm_x4(al[mt], aBaseL + mt * 16 * PITCH + ks * 32);
            }
            #pragma unroll
            for (int nh = 0; nh < 2; nh++) {
                ldm_x4(bhv[nh], bBaseH + nh * 16 * PITCH + ks * 32);
                ldm_x4(blv[nh], bBaseL + nh * 16 * PITCH + ks * 32);
            }
            #pragma unroll
            for (int mt = 0; mt < 2; mt++)
                #pragma unroll
                for (int nt = 0; nt < 4; nt++) {
                    const uint32_t* bhreg = &bhv[nt >> 1][(nt & 1) * 2];
                    const uint32_t* blreg = &blv[nt >> 1][(nt & 1) * 2];
                    mma16816(acc[mt][nt], ah[mt], bhreg);
                    mma16816(acc[mt][nt], al[mt], bhreg);
                    mma16816(acc[mt][nt], ah[mt], blreg);
                }
        }
    }

    const int g = lane >> 2, t = lane & 3;
    #pragma unroll
    for (int mt = 0; mt < 2; mt++)
        #pragma unroll
        for (int nt = 0; nt < 4; nt++) {
            int row0 = bm + wm * 32 + mt * 16 + g;
            int col  = wn * 32 + nt * 8 + t * 2;
            *(float2*)&C[(size_t)row0 * 128 + col] =
                make_float2(acc[mt][nt][0], acc[mt][nt][1]);
            *(float2*)&C[(size_t)(row0 + 8) * 128 + col] =
                make_float2(acc[mt][nt][2], acc[mt][nt][3]);
        }
}

// ============================================================================
// Kernel A (NEW): tensor-core attention.
// Per block: batch b, i-half h (64 rows). grid (64, 2). 256 thr = 8 warps 2x4.
//   S_id,k  = (H_rows ⊙ a_k) · H^T           (3-pass bf16 split)
//   S_abs,k = (|H_rows| ⊙ a_k) · |H|^T       (abs via register bit-ops)
//   alpha[i,j] = select by adj; softmax rows; out = attn · H (split GEMM).
// ============================================================================
#define PB      272                       // bytes per 128-bf16 row (+16 pad)
#define HB_H    0                         // H  [j][d] hi   (128 rows)
#define HB_L    34816                     // H  [j][d] lo
#define HT_H    69632                     // H^T[d][j] hi   (128 rows)
#define HT_L    104448                    // H^T[d][j] lo
#define AK_H    139264                    // A_k [i][d] hi  (64 rows)
#define AK_L    156672                    // A_k [i][d] lo
#define S_W     (139264 / 4)              // S overlay on AK (64 x 132 f32)
#define ATT_H   0                         // attn hi overlay on HB_H (64 rows)
#define ATT_L   17408                     // attn lo
#define A_SW    (174080 / 4)              // a_s f32[512]
#define SGN_W   (176128 / 4)              // sgn table u32[256]
#define SMEM_ATTN_TC 177152

__global__ void __launch_bounds__(256)
attn_tc_kernel(const float* __restrict__ hidden,   // [64,128,128]
               const int*   __restrict__ adj,      // [64,128,128]
               const float* __restrict__ a,        // [128,4]
               float*       __restrict__ out)      // [64,128,128]
{
    char*     smem  = dyn_smem;
    float*    smemf = (float*)dyn_smem;
    uint32_t* sgn_s = (uint32_t*)dyn_smem + SGN_W;
    float*    a_s   = smemf + A_SW;
    const uint32_t sb = s2u(smem);

    const int tid  = threadIdx.x;
    const int wid  = tid >> 5;
    const int lane = tid & 31;
    const int b    = blockIdx.x;
    const int ibase = b * 128 + blockIdx.y * 64;

    const int wm = wid >> 2, wn = wid & 3;
    const int g = lane >> 2, t = lane & 3;
    const uint32_t aOff = (uint32_t)((lane & 15) * PB + (lane >> 4) * 16);
    const uint32_t bOff = (uint32_t)(((((lane >> 4) & 1) << 3) + (lane & 7)) * PB
                                     + ((lane >> 3) & 1) * 16);

    // ---- stage H -> HB [j][d] and HT [d][j], bf16 hi/lo ----
    for (int q = tid; q < 16384; q += 256) {
        int d = q & 127, j = q >> 7;
        float v = hidden[(size_t)(b * 128 + j) * 128 + d];
        __nv_bfloat16 vh = __float2bfloat16(v);
        __nv_bfloat16 vl = __float2bfloat16(v - __bfloat162float(vh));
        *(__nv_bfloat16*)(smem + HB_H + j * PB + d * 2) = vh;
        *(__nv_bfloat16*)(smem + HB_L + j * PB + d * 2) = vl;
        *(__nv_bfloat16*)(smem + HT_H + d * PB + j * 2) = vh;
        *(__nv_bfloat16*)(smem + HT_L + d * PB + j * 2) = vl;
    }
    for (int q = tid; q < 512; q += 256) a_s[q] = a[q];
    {   // sign table: per (k,ks,t,half): sign bits of a_k at the frag's d-pair
        int kk = tid >> 6, ks = (tid >> 3) & 7, tt = (tid >> 1) & 3, hf = tid & 1;
        int d0 = ks * 16 + 2 * tt + hf * 8;
        uint32_t m = (a[d0 * 4 + kk] < 0.f ? 0x8000u : 0u)
                   | (a[(d0 + 1) * 4 + kk] < 0.f ? 0x80000000u : 0u);
        sgn_s[tid] = m;
    }

    // ---- adj -> per-k match bitmasks at this thread's 32 fragment coords ----
    uint32_t km0 = 0, km1 = 0, km2 = 0, km3 = 0;
    #pragma unroll
    for (int mt = 0; mt < 2; mt++)
        #pragma unroll
        for (int nt = 0; nt < 4; nt++)
            #pragma unroll
            for (int q = 0; q < 4; q++) {
                int il = wm * 32 + mt * 16 + g + (q >> 1) * 8;
                int j  = wn * 32 + nt * 8 + 2 * t + (q & 1);
                int av = adj[(size_t)(ibase + il) * 128 + j];
                int p  = (mt * 4 + nt) * 4 + q;
                km0 |= (uint32_t)(av == 1) << p;
                km1 |= (uint32_t)(av == 2) << p;
                km2 |= (uint32_t)(av == 3) << p;
                km3 |= (uint32_t)(av == 4) << p;
            }

    float alpha[2][4][4];
    #pragma unroll
    for (int mt = 0; mt < 2; mt++)
        #pragma unroll
        for (int nt = 0; nt < 4; nt++)
            #pragma unroll
            for (int q = 0; q < 4; q++) alpha[mt][nt][q] = NEG_INF_F;

    const int arow = tid >> 2, dseg = (tid & 3) * 32;

    // ==================== k-loop: 4 edge types ====================
    #pragma unroll 1
    for (int k = 0; k < 4; k++) {
        __syncthreads();   // staging visible (k=0) / prior GEMM reads done (k>0)

        // stage A_k = H rows(ibase..) * a_k, bf16 hi/lo
        {
            const float* hrow = hidden + (size_t)(ibase + arow) * 128 + dseg;
            #pragma unroll
            for (int gq = 0; gq < 4; gq++) {
                float4 x = *(const float4*)(hrow + gq * 8);
                float4 y = *(const float4*)(hrow + gq * 8 + 4);
                float f[8] = {x.x, x.y, x.z, x.w, y.x, y.y, y.z, y.w};
                uint32_t hw[4], lw[4];
                #pragma unroll
                for (int r = 0; r < 4; r++) {
                    int d0 = dseg + gq * 8 + 2 * r;
                    float f0 = f[2*r]     * a_s[d0 * 4 + k];
                    float f1 = f[2*r + 1] * a_s[(d0 + 1) * 4 + k];
                    __nv_bfloat16 h0 = __float2bfloat16(f0);
                    __nv_bfloat16 h1 = __float2bfloat16(f1);
                    hw[r] = pack_bf2(f0, f1);
                    lw[r] = pack_bf2(f0 - __bfloat162float(h0),
                                     f1 - __bfloat162float(h1));
                }
                *(uint4*)(smem + AK_H + arow * PB + (dseg + gq * 8) * 2) =
                    make_uint4(hw[0], hw[1], hw[2], hw[3]);
                *(uint4*)(smem + AK_L + arow * PB + (dseg + gq * 8) * 2) =
                    make_uint4(lw[0], lw[1], lw[2], lw[3]);
            }
        }
        __syncthreads();

        float Sid[2][4][4], Sab[2][4][4];
        #pragma unroll
        for (int mt = 0; mt < 2; mt++)
            #pragma unroll
            for (int nt = 0; nt < 4; nt++)
                #pragma unroll
                for (int q = 0; q < 4; q++) { Sid[mt][nt][q] = 0.f; Sab[mt][nt][q] = 0.f; }

        const uint32_t akh = sb + AK_H + (uint32_t)(wm * 32 * PB) + aOff;
        const uint32_t akl = sb + AK_L + (uint32_t)(wm * 32 * PB) + aOff;
        const uint32_t hbh = sb + HB_H + (uint32_t)(wn * 32 * PB) + bOff;
        const uint32_t hbl = sb + HB_L + (uint32_t)(wn * 32 * PB) + bOff;

        #pragma unroll
        for (int ks = 0; ks < 8; ks++) {
            uint32_t ah[2][4], al[2][4], bh[2][4], bl[2][4];
            #pragma unroll
            for (int mt = 0; mt < 2; mt++) {
                ldm_x4(ah[mt], akh + mt * 16 * PB + ks * 32);
                ldm_x4(al[mt], akl + mt * 16 * PB + ks * 32);
            }
            #pragma unroll
            for (int nh = 0; nh < 2; nh++) {
                ldm_x4(bh[nh], hbh + nh * 16 * PB + ks * 32);
                ldm_x4(bl[nh], hbl + nh * 16 * PB + ks * 32);
            }

            // identity-term mmas first (frags still original)
            #pragma unroll
            for (int mt = 0; mt < 2; mt++)
                #pragma unroll
                for (int nt = 0; nt < 4; nt++) {
                    const uint32_t* bhr = &bh[nt >> 1][(nt & 1) * 2];
                    const uint32_t* blr = &bl[nt >> 1][(nt & 1) * 2];
                    mma16816(Sid[mt][nt], ah[mt], bhr);
                    mma16816(Sid[mt][nt], al[mt], bhr);
                    mma16816(Sid[mt][nt], ah[mt], blr);
                }

            // transform frags in place to abs variants:
            //  A~h = (Ah & 0x7FFF7FFF) ^ m ;  A~l = Al ^ (Ah & 0x80008000) ^ m
            //  B~h =  Bh & 0x7FFF7FFF      ;  B~l = Bl ^ (Bh & 0x80008000)
            uint32_t m01 = sgn_s[((k * 8 + ks) * 4 + t) * 2];
            uint32_t m23 = sgn_s[((k * 8 + ks) * 4 + t) * 2 + 1];
            #pragma unroll
            for (int mt = 0; mt < 2; mt++)
                #pragma unroll
                for (int r = 0; r < 4; r++) {
                    uint32_t mm = (r < 2) ? m01 : m23;
                    al[mt][r] = al[mt][r] ^ (ah[mt][r] & 0x80008000u) ^ mm;
                    ah[mt][r] = (ah[mt][r] & 0x7FFF7FFFu) ^ mm;
                }
            #pragma unroll
            for (int nh = 0; nh < 2; nh++)
                #pragma unroll
                for (int r = 0; r < 4; r++) {
                    bl[nh][r] = bl[nh][r] ^ (bh[nh][r] & 0x80008000u);
                    bh[nh][r] = bh[nh][r] & 0x7FFF7FFFu;
                }

            #pragma unroll
            for (int mt = 0; mt < 2; mt++)
                #pragma unroll
                for (int nt = 0; nt < 4; nt++) {
                    const uint32_t* bhr = &bh[nt >> 1][(nt & 1) * 2];
                    const uint32_t* blr = &bl[nt >> 1][(nt & 1) * 2];
                    mma16816(Sab[mt][nt], ah[mt], bhr);
                    mma16816(Sab[mt][nt], al[mt], bhr);
                    mma16816(Sab[mt][nt], ah[mt], blr);
                }
        }

        // masked select into alpha
        uint32_t mk = (k == 0) ? km0 : (k == 1) ? km1 : (k == 2) ? km2 : km3;
        #pragma unroll
        for (int mt = 0; mt < 2; mt++)
            #pragma unroll
            for (int nt = 0; nt < 4; nt++)
                #pragma unroll
                for (int q = 0; q < 4; q++) {
                    float combo = fmaf(0.6f, Sid[mt][nt][q], 0.4f * Sab[mt][nt][q]);
                    int p = (mt * 4 + nt) * 4 + q;
                    if ((mk >> p) & 1u) alpha[mt][nt][q] = combo;
                }
    }

    // ---- write alpha to S (overlay on AK; AK reads done) ----
    __syncthreads();
    #pragma unroll
    for (int mt = 0; mt < 2; mt++)
        #pragma unroll
        for (int nt = 0; nt < 4; nt++) {
            int il = wm * 32 + mt * 16 + g;
            int jc = wn * 32 + nt * 8 + 2 * t;
            *(float2*)(smemf + S_W + il * 132 + jc) =
                make_float2(alpha[mt][nt][0], alpha[mt][nt][1]);
            *(float2*)(smemf + S_W + (il + 8) * 132 + jc) =
                make_float2(alpha[mt][nt][2], alpha[mt][nt][3]);
        }
    __syncthreads();

    // ---- softmax: warp handles 8 rows ----
    for (int r = wid * 8; r < wid * 8 + 8; r++) {
        float* srow = smemf + S_W + r * 132;
        float v0 = srow[lane], v1 = srow[lane + 32];
        float v2 = srow[lane + 64], v3 = srow[lane + 96];
        float mx = fmaxf(fmaxf(v0, v1), fmaxf(v2, v3));
        #pragma unroll
        for (int o = 16; o; o >>= 1)
            mx = fmaxf(mx, __shfl_xor_sync(0xffffffffu, mx, o));
        float e0 = __expf(v0 - mx), e1 = __expf(v1 - mx);
        float e2 = __expf(v2 - mx), e3 = __expf(v3 - mx);
        float sm = (e0 + e1) + (e2 + e3);
        #pragma unroll
        for (int o = 16; o; o >>= 1)
            sm += __shfl_xor_sync(0xffffffffu, sm, o);
        float inv = 1.f / sm;
        srow[lane]      = e0 * inv;
        srow[lane + 32] = e1 * inv;
        srow[lane + 64] = e2 * inv;
        srow[lane + 96] = e3 * inv;
    }
    __syncthreads();

    // ---- attn -> bf16 hi/lo tiles (overlay HB region; HB reads done) ----
    {
        int row = tid >> 2, jseg = (tid & 3) * 32;
        const float* srow = smemf + S_W + row * 132 + jseg;
        #pragma unroll
        for (int gq = 0; gq < 4; gq++) {
            uint32_t hw[4], lw[4];
            #pragma unroll
            for (int r = 0; r < 4; r++) {
                float f0 = srow[gq * 8 + 2 * r];
                float f1 = srow[gq * 8 + 2 * r + 1];
                __nv_bfloat16 h0 = __float2bfloat16(f0);
                __nv_bfloat16 h1 = __float2bfloat16(f1);
                hw[r] = pack_bf2(f0, f1);
                lw[r] = pack_bf2(f0 - __bfloat162float(h0),
                                 f1 - __bfloat162float(h1));
            }
            *(uint4*)(smem + ATT_H + row * PB + (jseg + gq * 8) * 2) =
                make_uint4(hw[0], hw[1], hw[2], hw[3]);
            *(uint4*)(smem + ATT_L + row * PB + (jseg + gq * 8) * 2) =
                make_uint4(lw[0], lw[1], lw[2], lw[3]);
        }
    }
    __syncthreads();

    // ---- AV GEMM: out = attn @ H  (A = attn [i][j], B = HT [d][j]) ----
    float O[2][4][4];
    #pragma unroll
    for (int mt = 0; mt < 2; mt++)
        #pragma unroll
        for (int nt = 0; nt < 4; nt++)
            #pragma unroll
            for (int q = 0; q < 4; q++) O[mt][nt][q] = 0.f;

    const uint32_t ath = sb + ATT_H + (uint32_t)(wm * 32 * PB) + aOff;
    const uint32_t atl = sb + ATT_L + (uint32_t)(wm * 32 * PB) + aOff;
    const uint32_t hth = sb + HT_H + (uint32_t)(wn * 32 * PB) + bOff;
    const uint32_t htl = sb + HT_L + (uint32_t)(wn * 32 * PB) + bOff;

    #pragma unroll
    for (int ks = 0; ks < 8; ks++) {
        uint32_t ah[2][4], al[2][4], bh[2][4], bl[2][4];
        #pragma unroll
        for (int mt = 0; mt < 2; mt++) {
            ldm_x4(ah[mt], ath + mt * 16 * PB + ks * 32);
            ldm_x4(al[mt], atl + mt * 16 * PB + ks * 32);
        }
        #pragma unroll
        for (int nh = 0; nh < 2; nh++) {
            ldm_x4(bh[nh], hth + nh * 16 * PB + ks * 32);
            ldm_x4(bl[nh], htl + nh * 16 * PB + ks * 32);
        }
        #pragma unroll
        for (int mt = 0; mt < 2; mt++)
            #pragma unroll
            for (int nt = 0; nt < 4; nt++) {
                const uint32_t* bhr = &bh[nt >> 1][(nt & 1) * 2];
                const uint32_t* blr = &bl[nt >> 1][(nt & 1) * 2];
                mma16816(O[mt][nt], ah[mt], bhr);
                mma16816(O[mt][nt], al[mt], bhr);
                mma16816(O[mt][nt], ah[mt], blr);
            }
    }

    #pragma unroll
    for (int mt = 0; mt < 2; mt++)
        #pragma unroll
        for (int nt = 0; nt < 4; nt++) {
            int row0 = ibase + wm * 32 + mt * 16 + g;
            int col  = wn * 32 + nt * 8 + t * 2;
            *(float2*)&out[(size_t)row0 * 128 + col] =
                make_float2(O[mt][nt][0], O[mt][nt][1]);
            *(float2*)&out[(size_t)(row0 + 8) * 128 + col] =
                make_float2(O[mt][nt][2], O[mt][nt][3]);
        }
}

// ============================================================================
extern "C" void kernel_launch(void* const* d_in, const int* in_sizes, int n_in,
                              void* d_out, int out_size)
{
    const float* hidden   = (const float*)d_in[0];  // [64,128,128]
    const int*   adj      = (const int*)  d_in[1];  // [64,128,128]
    const float* a        = (const float*)d_in[2];  // [128,4]
    const float* A_attr   = (const float*)d_in[3];  // [64,128,1000]
    const float* attr_emb = (const float*)d_in[4];  // [1000,128]

    float* out       = (float*)d_out;
    float* out_attn  = out;                   // output    [64,128,128]
    float* out_attr  = out + 64 * 128 * 128;  // attr_sess [64,128,128]

    cudaFuncSetAttribute(attn_tc_kernel,
                         cudaFuncAttributeMaxDynamicSharedMemorySize, SMEM_ATTN_TC);
    cudaFuncSetAttribute(attr_gemm_mma,
                         cudaFuncAttributeMaxDynamicSharedMemorySize, SMEM_GEMM);

    bconv_kernel<<<512, 256>>>(attr_emb);
    attn_tc_kernel<<<dim3(64, 2), 256, SMEM_ATTN_TC>>>(hidden, adj, a, out_attn);
    attr_gemm_mma<<<128, 256, SMEM_GEMM>>>(A_attr, out_attr);
}

// round 14
// speedup vs baseline: 1.7561x; 1.0433x over previous
#include <cuda_runtime.h>
#include <cuda_bf16.h>
#include <cstdint>
#include <math.h>

#define NEG_INF_F   (-9.0e15f)

extern __shared__ char dyn_smem[];

// ============================================================================
// Helpers (battle-tested)
// ============================================================================
__device__ __forceinline__ uint32_t s2u(const void* p) {
    uint32_t a;
    asm("{ .reg .u64 t; cvta.to.shared.u64 t, %1; cvt.u32.u64 %0, t; }"
        : "=r"(a) : "l"(p));
    return a;
}
__device__ __forceinline__ void ldm_x4(uint32_t* r, uint32_t addr) {
    asm volatile("ldmatrix.sync.aligned.m8n8.x4.shared.b16 {%0,%1,%2,%3}, [%4];"
                 : "=r"(r[0]), "=r"(r[1]), "=r"(r[2]), "=r"(r[3]) : "r"(addr));
}
__device__ __forceinline__ void mma16816(float* c, const uint32_t* a, const uint32_t* b) {
    asm volatile(
        "mma.sync.aligned.m16n8k16.row.col.f32.bf16.bf16.f32 "
        "{%0,%1,%2,%3}, {%4,%5,%6,%7}, {%8,%9}, {%0,%1,%2,%3};"
        : "+f"(c[0]), "+f"(c[1]), "+f"(c[2]), "+f"(c[3])
        : "r"(a[0]), "r"(a[1]), "r"(a[2]), "r"(a[3]), "r"(b[0]), "r"(b[1]));
}
__device__ __forceinline__ uint32_t pack_bf2(float a, float b) {
    __nv_bfloat162 t = __floats2bfloat162_rn(a, b);
    return *(uint32_t*)&t;
}

// ============================================================================
// Device scratch: B^T in bf16 hi/lo, K padded to 1024 (zeros). Bt[n][k]=B[k][n]
// ============================================================================
__device__ __nv_bfloat16 g_Bh[128 * 1024];
__device__ __nv_bfloat16 g_Bl[128 * 1024];

__global__ void __launch_bounds__(256) bconv_kernel(const float* __restrict__ B) {
    int idx = blockIdx.x * 256 + threadIdx.x;   // 131072
    int n = idx & 127;
    int k = idx >> 7;
    float v = (k < 1000) ? B[k * 128 + n] : 0.f;
    __nv_bfloat16 h = __float2bfloat16(v);
    g_Bh[n * 1024 + k] = h;
    g_Bl[n * 1024 + k] = __float2bfloat16(v - __bfloat162float(h));
}

// ============================================================================
// Kernel B: attr GEMM, warp-level bf16 mma.sync split (unchanged, proven)
// ============================================================================
#define GK     1000
#define CH     64
#define NCH    16
#define PITCH  144
#define SA_H   0
#define SA_L   (64 * PITCH)
#define SB_H   (2 * 64 * PITCH)
#define SB_L   (SB_H + 128 * PITCH)
#define SMEM_GEMM (SB_L + 128 * PITCH)      // 55296

__global__ void __launch_bounds__(256)
attr_gemm_mma(const float* __restrict__ A, float* __restrict__ C) {
    char* smem = dyn_smem;
    const uint32_t sb = s2u(smem);
    const int tid  = threadIdx.x;
    const int wid  = tid >> 5;
    const int lane = tid & 31;
    const int bm   = blockIdx.x * 64;
    const int wm = wid >> 2;
    const int wn = wid & 3;

    const uint32_t aOff = (uint32_t)((lane & 15) * PITCH + (lane >> 4) * 16);
    const uint32_t bOff = (uint32_t)(((((lane >> 4) & 1) << 3) + (lane & 7)) * PITCH
                                     + ((lane >> 3) & 1) * 16);

    const int arow = tid >> 2, akseg = tid & 3;
    const int brow = tid >> 1, bseg  = tid & 1;
    const float* aptr = A + (size_t)(bm + arow) * GK;
    const __nv_bfloat16* bhp = g_Bh + brow * 1024 + bseg * 32;
    const __nv_bfloat16* blp = g_Bl + brow * 1024 + bseg * 32;

    float  as[16];
    uint4  bh4[4], bl4[4];

    {
        const float4* ap4 = (const float4*)(aptr + akseg * 16);
        #pragma unroll
        for (int i = 0; i < 4; i++) {
            float4 v = ap4[i];
            as[4*i+0] = v.x; as[4*i+1] = v.y; as[4*i+2] = v.z; as[4*i+3] = v.w;
        }
        #pragma unroll
        for (int i = 0; i < 4; i++) {
            bh4[i] = *(const uint4*)(bhp + i * 8);
            bl4[i] = *(const uint4*)(blp + i * 8);
        }
    }

    float acc[2][4][4];
    #pragma unroll
    for (int mt = 0; mt < 2; mt++)
        #pragma unroll
        for (int nt = 0; nt < 4; nt++)
            #pragma unroll
            for (int q = 0; q < 4; q++) acc[mt][nt][q] = 0.f;

    #pragma unroll 1
    for (int c = 0; c < NCH; c++) {
        if (c > 0) __syncthreads();

        {
            char* pa = smem + SA_H + arow * PITCH + akseg * 32;
            char* pl = smem + SA_L + arow * PITCH + akseg * 32;
            uint4 hv, lv;
            #pragma unroll
            for (int half = 0; half < 2; half++) {
                const float* f = as + half * 8;
                __nv_bfloat16 h0 = __float2bfloat16(f[0]), h1 = __float2bfloat16(f[1]);
                __nv_bfloat16 h2 = __float2bfloat16(f[2]), h3 = __float2bfloat16(f[3]);
                __nv_bfloat16 h4 = __float2bfloat16(f[4]), h5 = __float2bfloat16(f[5]);
                __nv_bfloat16 h6 = __float2bfloat16(f[6]), h7 = __float2bfloat16(f[7]);
                hv.x = pack_bf2(f[0], f[1]); hv.y = pack_bf2(f[2], f[3]);
                hv.z = pack_bf2(f[4], f[5]); hv.w = pack_bf2(f[6], f[7]);
                lv.x = pack_bf2(f[0]-__bfloat162float(h0), f[1]-__bfloat162float(h1));
                lv.y = pack_bf2(f[2]-__bfloat162float(h2), f[3]-__bfloat162float(h3));
                lv.z = pack_bf2(f[4]-__bfloat162float(h4), f[5]-__bfloat162float(h5));
                lv.w = pack_bf2(f[6]-__bfloat162float(h6), f[7]-__bfloat162float(h7));
                *(uint4*)(pa + half * 16) = hv;
                *(uint4*)(pl + half * 16) = lv;
            }
            char* pbh = smem + SB_H + brow * PITCH + bseg * 64;
            char* pbl = smem + SB_L + brow * PITCH + bseg * 64;
            #pragma unroll
            for (int i = 0; i < 4; i++) {
                *(uint4*)(pbh + i * 16) = bh4[i];
                *(uint4*)(pbl + i * 16) = bl4[i];
            }
        }
        __syncthreads();

        if (c + 1 < NCH) {
            const int k0 = (c + 1) * CH;
            if (c + 1 < NCH - 1) {
                const float4* ap4 = (const float4*)(aptr + k0 + akseg * 16);
                #pragma unroll
                for (int i = 0; i < 4; i++) {
                    float4 v = ap4[i];
                    as[4*i+0]=v.x; as[4*i+1]=v.y; as[4*i+2]=v.z; as[4*i+3]=v.w;
                }
            } else {
                #pragma unroll
                for (int i = 0; i < 16; i++) {
                    int kg = k0 + akseg * 16 + i;
                    as[i] = (kg < GK) ? aptr[kg] : 0.f;
                }
            }
            #pragma unroll
            for (int i = 0; i < 4; i++) {
                bh4[i] = *(const uint4*)(bhp + k0 + i * 8);
                bl4[i] = *(const uint4*)(blp + k0 + i * 8);
            }
        }

        const uint32_t aBaseH = sb + SA_H + (uint32_t)(wm * 32 * PITCH) + aOff;
        const uint32_t aBaseL = sb + SA_L + (uint32_t)(wm * 32 * PITCH) + aOff;
        const uint32_t bBaseH = sb + SB_H + (uint32_t)(wn * 32 * PITCH) + bOff;
        const uint32_t bBaseL = sb + SB_L + (uint32_t)(wn * 32 * PITCH) + bOff;

        #pragma unroll
        for (int ks = 0; ks < 4; ks++) {
            uint32_t ah[2][4], al[2][4], bhv[2][4], blv[2][4];
            #pragma unroll
            for (int mt = 0; mt < 2; mt++) {
                ldm_x4(ah[mt], aBaseH + mt * 16 * PITCH + ks * 32);
                ldm_x4(al[mt], aBaseL + mt * 16 * PITCH + ks * 32);
            }
            #pragma unroll
            for (int nh = 0; nh < 2; nh++) {
                ldm_x4(bhv[nh], bBaseH + nh * 16 * PITCH + ks * 32);
                ldm_x4(blv[nh], bBaseL + nh * 16 * PITCH + ks * 32);
            }
            #pragma unroll
            for (int mt = 0; mt < 2; mt++)
                #pragma unroll
                for (int nt = 0; nt < 4; nt++) {
                    const uint32_t* bhreg = &bhv[nt >> 1][(nt & 1) * 2];
                    const uint32_t* blreg = &blv[nt >> 1][(nt & 1) * 2];
                    mma16816(acc[mt][nt], ah[mt], bhreg);
                    mma16816(acc[mt][nt], al[mt], bhreg);
                    mma16816(acc[mt][nt], ah[mt], blreg);
                }
        }
    }

    const int g = lane >> 2, t = lane & 3;
    #pragma unroll
    for (int mt = 0; mt < 2; mt++)
        #pragma unroll
        for (int nt = 0; nt < 4; nt++) {
            int row0 = bm + wm * 32 + mt * 16 + g;
            int col  = wn * 32 + nt * 8 + t * 2;
            *(float2*)&C[(size_t)row0 * 128 + col] =
                make_float2(acc[mt][nt][0], acc[mt][nt][1]);
            *(float2*)&C[(size_t)(row0 + 8) * 128 + col] =
                make_float2(acc[mt][nt][2], acc[mt][nt][3]);
        }
}

// ============================================================================
// Kernel A: tensor-core attention (unchanged from R13 — proven)
// ============================================================================
#define PB      272
#define HB_H    0
#define HB_L    34816
#define HT_H    69632
#define HT_L    104448
#define AK_H    139264
#define AK_L    156672
#define S_W     (139264 / 4)
#define ATT_H   0
#define ATT_L   17408
#define A_SW    (174080 / 4)
#define SGN_W   (176128 / 4)
#define SMEM_ATTN_TC 177152

__global__ void __launch_bounds__(256)
attn_tc_kernel(const float* __restrict__ hidden,
               const int*   __restrict__ adj,
               const float* __restrict__ a,
               float*       __restrict__ out)
{
    char*     smem  = dyn_smem;
    float*    smemf = (float*)dyn_smem;
    uint32_t* sgn_s = (uint32_t*)dyn_smem + SGN_W;
    float*    a_s   = smemf + A_SW;
    const uint32_t sb = s2u(smem);

    const int tid  = threadIdx.x;
    const int wid  = tid >> 5;
    const int lane = tid & 31;
    const int b    = blockIdx.x;
    const int ibase = b * 128 + blockIdx.y * 64;

    const int wm = wid >> 2, wn = wid & 3;
    const int g = lane >> 2, t = lane & 3;
    const uint32_t aOff = (uint32_t)((lane & 15) * PB + (lane >> 4) * 16);
    const uint32_t bOff = (uint32_t)(((((lane >> 4) & 1) << 3) + (lane & 7)) * PB
                                     + ((lane >> 3) & 1) * 16);

    for (int q = tid; q < 16384; q += 256) {
        int d = q & 127, j = q >> 7;
        float v = hidden[(size_t)(b * 128 + j) * 128 + d];
        __nv_bfloat16 vh = __float2bfloat16(v);
        __nv_bfloat16 vl = __float2bfloat16(v - __bfloat162float(vh));
        *(__nv_bfloat16*)(smem + HB_H + j * PB + d * 2) = vh;
        *(__nv_bfloat16*)(smem + HB_L + j * PB + d * 2) = vl;
        *(__nv_bfloat16*)(smem + HT_H + d * PB + j * 2) = vh;
        *(__nv_bfloat16*)(smem + HT_L + d * PB + j * 2) = vl;
    }
    for (int q = tid; q < 512; q += 256) a_s[q] = a[q];
    {
        int kk = tid >> 6, ks = (tid >> 3) & 7, tt = (tid >> 1) & 3, hf = tid & 1;
        int d0 = ks * 16 + 2 * tt + hf * 8;
        uint32_t m = (a[d0 * 4 + kk] < 0.f ? 0x8000u : 0u)
                   | (a[(d0 + 1) * 4 + kk] < 0.f ? 0x80000000u : 0u);
        sgn_s[tid] = m;
    }

    uint32_t km0 = 0, km1 = 0, km2 = 0, km3 = 0;
    #pragma unroll
    for (int mt = 0; mt < 2; mt++)
        #pragma unroll
        for (int nt = 0; nt < 4; nt++)
            #pragma unroll
            for (int q = 0; q < 4; q++) {
                int il = wm * 32 + mt * 16 + g + (q >> 1) * 8;
                int j  = wn * 32 + nt * 8 + 2 * t + (q & 1);
                int av = adj[(size_t)(ibase + il) * 128 + j];
                int p  = (mt * 4 + nt) * 4 + q;
                km0 |= (uint32_t)(av == 1) << p;
                km1 |= (uint32_t)(av == 2) << p;
                km2 |= (uint32_t)(av == 3) << p;
                km3 |= (uint32_t)(av == 4) << p;
            }

    float alpha[2][4][4];
    #pragma unroll
    for (int mt = 0; mt < 2; mt++)
        #pragma unroll
        for (int nt = 0; nt < 4; nt++)
            #pragma unroll
            for (int q = 0; q < 4; q++) alpha[mt][nt][q] = NEG_INF_F;

    const int arow = tid >> 2, dseg = (tid & 3) * 32;

    #pragma unroll 1
    for (int k = 0; k < 4; k++) {
        __syncthreads();

        {
            const float* hrow = hidden + (size_t)(ibase + arow) * 128 + dseg;
            #pragma unroll
            for (int gq = 0; gq < 4; gq++) {
                float4 x = *(const float4*)(hrow + gq * 8);
                float4 y = *(const float4*)(hrow + gq * 8 + 4);
                float f[8] = {x.x, x.y, x.z, x.w, y.x, y.y, y.z, y.w};
                uint32_t hw[4], lw[4];
                #pragma unroll
                for (int r = 0; r < 4; r++) {
                    int d0 = dseg + gq * 8 + 2 * r;
                    float f0 = f[2*r]     * a_s[d0 * 4 + k];
                    float f1 = f[2*r + 1] * a_s[(d0 + 1) * 4 + k];
                    __nv_bfloat16 h0 = __float2bfloat16(f0);
                    __nv_bfloat16 h1 = __float2bfloat16(f1);
                    hw[r] = pack_bf2(f0, f1);
                    lw[r] = pack_bf2(f0 - __bfloat162float(h0),
                                     f1 - __bfloat162float(h1));
                }
                *(uint4*)(smem + AK_H + arow * PB + (dseg + gq * 8) * 2) =
                    make_uint4(hw[0], hw[1], hw[2], hw[3]);
                *(uint4*)(smem + AK_L + arow * PB + (dseg + gq * 8) * 2) =
                    make_uint4(lw[0], lw[1], lw[2], lw[3]);
            }
        }
        __syncthreads();

        float Sid[2][4][4], Sab[2][4][4];
        #pragma unroll
        for (int mt = 0; mt < 2; mt++)
            #pragma unroll
            for (int nt = 0; nt < 4; nt++)
                #pragma unroll
                for (int q = 0; q < 4; q++) { Sid[mt][nt][q] = 0.f; Sab[mt][nt][q] = 0.f; }

        const uint32_t akh = sb + AK_H + (uint32_t)(wm * 32 * PB) + aOff;
        const uint32_t akl = sb + AK_L + (uint32_t)(wm * 32 * PB) + aOff;
        const uint32_t hbh = sb + HB_H + (uint32_t)(wn * 32 * PB) + bOff;
        const uint32_t hbl = sb + HB_L + (uint32_t)(wn * 32 * PB) + bOff;

        #pragma unroll
        for (int ks = 0; ks < 8; ks++) {
            uint32_t ah[2][4], al[2][4], bh[2][4], bl[2][4];
            #pragma unroll
            for (int mt = 0; mt < 2; mt++) {
                ldm_x4(ah[mt], akh + mt * 16 * PB + ks * 32);
                ldm_x4(al[mt], akl + mt * 16 * PB + ks * 32);
            }
            #pragma unroll
            for (int nh = 0; nh < 2; nh++) {
                ldm_x4(bh[nh], hbh + nh * 16 * PB + ks * 32);
                ldm_x4(bl[nh], hbl + nh * 16 * PB + ks * 32);
            }

            #pragma unroll
            for (int mt = 0; mt < 2; mt++)
                #pragma unroll
                for (int nt = 0; nt < 4; nt++) {
                    const uint32_t* bhr = &bh[nt >> 1][(nt & 1) * 2];
                    const uint32_t* blr = &bl[nt >> 1][(nt & 1) * 2];
                    mma16816(Sid[mt][nt], ah[mt], bhr);
                    mma16816(Sid[mt][nt], al[mt], bhr);
                    mma16816(Sid[mt][nt], ah[mt], blr);
                }

            uint32_t m01 = sgn_s[((k * 8 + ks) * 4 + t) * 2];
            uint32_t m23 = sgn_s[((k * 8 + ks) * 4 + t) * 2 + 1];
            #pragma unroll
            for (int mt = 0; mt < 2; mt++)
                #pragma unroll
                for (int r = 0; r < 4; r++) {
                    uint32_t mm = (r < 2) ? m01 : m23;
                    al[mt][r] = al[mt][r] ^ (ah[mt][r] & 0x80008000u) ^ mm;
                    ah[mt][r] = (ah[mt][r] & 0x7FFF7FFFu) ^ mm;
                }
            #pragma unroll
            for (int nh = 0; nh < 2; nh++)
                #pragma unroll
                for (int r = 0; r < 4; r++) {
                    bl[nh][r] = bl[nh][r] ^ (bh[nh][r] & 0x80008000u);
                    bh[nh][r] = bh[nh][r] & 0x7FFF7FFFu;
                }

            #pragma unroll
            for (int mt = 0; mt < 2; mt++)
                #pragma unroll
                for (int nt = 0; nt < 4; nt++) {
                    const uint32_t* bhr = &bh[nt >> 1][(nt & 1) * 2];
                    const uint32_t* blr = &bl[nt >> 1][(nt & 1) * 2];
                    mma16816(Sab[mt][nt], ah[mt], bhr);
                    mma16816(Sab[mt][nt], al[mt], bhr);
                    mma16816(Sab[mt][nt], ah[mt], blr);
                }
        }

        uint32_t mk = (k == 0) ? km0 : (k == 1) ? km1 : (k == 2) ? km2 : km3;
        #pragma unroll
        for (int mt = 0; mt < 2; mt++)
            #pragma unroll
            for (int nt = 0; nt < 4; nt++)
                #pragma unroll
                for (int q = 0; q < 4; q++) {
                    float combo = fmaf(0.6f, Sid[mt][nt][q], 0.4f * Sab[mt][nt][q]);
                    int p = (mt * 4 + nt) * 4 + q;
                    if ((mk >> p) & 1u) alpha[mt][nt][q] = combo;
                }
    }

    __syncthreads();
    #pragma unroll
    for (int mt = 0; mt < 2; mt++)
        #pragma unroll
        for (int nt = 0; nt < 4; nt++) {
            int il = wm * 32 + mt * 16 + g;
            int jc = wn * 32 + nt * 8 + 2 * t;
            *(float2*)(smemf + S_W + il * 132 + jc) =
                make_float2(alpha[mt][nt][0], alpha[mt][nt][1]);
            *(float2*)(smemf + S_W + (il + 8) * 132 + jc) =
                make_float2(alpha[mt][nt][2], alpha[mt][nt][3]);
        }
    __syncthreads();

    for (int r = wid * 8; r < wid * 8 + 8; r++) {
        float* srow = smemf + S_W + r * 132;
        float v0 = srow[lane], v1 = srow[lane + 32];
        float v2 = srow[lane + 64], v3 = srow[lane + 96];
        float mx = fmaxf(fmaxf(v0, v1), fmaxf(v2, v3));
        #pragma unroll
        for (int o = 16; o; o >>= 1)
            mx = fmaxf(mx, __shfl_xor_sync(0xffffffffu, mx, o));
        float e0 = __expf(v0 - mx), e1 = __expf(v1 - mx);
        float e2 = __expf(v2 - mx), e3 = __expf(v3 - mx);
        float sm = (e0 + e1) + (e2 + e3);
        #pragma unroll
        for (int o = 16; o; o >>= 1)
            sm += __shfl_xor_sync(0xffffffffu, sm, o);
        float inv = 1.f / sm;
        srow[lane]      = e0 * inv;
        srow[lane + 32] = e1 * inv;
        srow[lane + 64] = e2 * inv;
        srow[lane + 96] = e3 * inv;
    }
    __syncthreads();

    {
        int row = tid >> 2, jseg = (tid & 3) * 32;
        const float* srow = smemf + S_W + row * 132 + jseg;
        #pragma unroll
        for (int gq = 0; gq < 4; gq++) {
            uint32_t hw[4], lw[4];
            #pragma unroll
            for (int r = 0; r < 4; r++) {
                float f0 = srow[gq * 8 + 2 * r];
                float f1 = srow[gq * 8 + 2 * r + 1];
                __nv_bfloat16 h0 = __float2bfloat16(f0);
                __nv_bfloat16 h1 = __float2bfloat16(f1);
                hw[r] = pack_bf2(f0, f1);
                lw[r] = pack_bf2(f0 - __bfloat162float(h0),
                                 f1 - __bfloat162float(h1));
            }
            *(uint4*)(smem + ATT_H + row * PB + (jseg + gq * 8) * 2) =
                make_uint4(hw[0], hw[1], hw[2], hw[3]);
            *(uint4*)(smem + ATT_L + row * PB + (jseg + gq * 8) * 2) =
                make_uint4(lw[0], lw[1], lw[2], lw[3]);
        }
    }
    __syncthreads();

    float O[2][4][4];
    #pragma unroll
    for (int mt = 0; mt < 2; mt++)
        #pragma unroll
        for (int nt = 0; nt < 4; nt++)
            #pragma unroll
            for (int q = 0; q < 4; q++) O[mt][nt][q] = 0.f;

    const uint32_t ath = sb + ATT_H + (uint32_t)(wm * 32 * PB) + aOff;
    const uint32_t atl = sb + ATT_L + (uint32_t)(wm * 32 * PB) + aOff;
    const uint32_t hth = sb + HT_H + (uint32_t)(wn * 32 * PB) + bOff;
    const uint32_t htl = sb + HT_L + (uint32_t)(wn * 32 * PB) + bOff;

    #pragma unroll
    for (int ks = 0; ks < 8; ks++) {
        uint32_t ah[2][4], al[2][4], bh[2][4], bl[2][4];
        #pragma unroll
        for (int mt = 0; mt < 2; mt++) {
            ldm_x4(ah[mt], ath + mt * 16 * PB + ks * 32);
            ldm_x4(al[mt], atl + mt * 16 * PB + ks * 32);
        }
        #pragma unroll
        for (int nh = 0; nh < 2; nh++) {
            ldm_x4(bh[nh], hth + nh * 16 * PB + ks * 32);
            ldm_x4(bl[nh], htl + nh * 16 * PB + ks * 32);
        }
        #pragma unroll
        for (int mt = 0; mt < 2; mt++)
            #pragma unroll
            for (int nt = 0; nt < 4; nt++) {
                const uint32_t* bhr = &bh[nt >> 1][(nt & 1) * 2];
                const uint32_t* blr = &bl[nt >> 1][(nt & 1) * 2];
                mma16816(O[mt][nt], ah[mt], bhr);
                mma16816(O[mt][nt], al[mt], bhr);
                mma16816(O[mt][nt], ah[mt], blr);
            }
    }

    #pragma unroll
    for (int mt = 0; mt < 2; mt++)
        #pragma unroll
        for (int nt = 0; nt < 4; nt++) {
            int row0 = ibase + wm * 32 + mt * 16 + g;
            int col  = wn * 32 + nt * 8 + t * 2;
            *(float2*)&out[(size_t)row0 * 128 + col] =
                make_float2(O[mt][nt][0], O[mt][nt][1]);
            *(float2*)&out[(size_t)(row0 + 8) * 128 + col] =
                make_float2(O[mt][nt][2], O[mt][nt][3]);
        }
}

// ============================================================================
// Launch: fork/join so attn_tc runs concurrently with bconv -> attr_gemm.
// Streams/events created once on first (uncaptured correctness) call; the
// captured per-call work is identical every time (graph-capture legal).
// ============================================================================
extern "C" void kernel_launch(void* const* d_in, const int* in_sizes, int n_in,
                              void* d_out, int out_size)
{
    const float* hidden   = (const float*)d_in[0];  // [64,128,128]
    const int*   adj      = (const int*)  d_in[1];  // [64,128,128]
    const float* a        = (const float*)d_in[2];  // [128,4]
    const float* A_attr   = (const float*)d_in[3];  // [64,128,1000]
    const float* attr_emb = (const float*)d_in[4];  // [1000,128]

    float* out       = (float*)d_out;
    float* out_attn  = out;                   // output    [64,128,128]
    float* out_attr  = out + 64 * 128 * 128;  // attr_sess [64,128,128]

    static cudaStream_t s_side = nullptr;
    static cudaEvent_t  ev_fork = nullptr, ev_join = nullptr;
    if (s_side == nullptr) {
        cudaStreamCreateWithFlags(&s_side, cudaStreamNonBlocking);
        cudaEventCreateWithFlags(&ev_fork, cudaEventDisableTiming);
        cudaEventCreateWithFlags(&ev_join, cudaEventDisableTiming);
        cudaFuncSetAttribute(attn_tc_kernel,
                             cudaFuncAttributeMaxDynamicSharedMemorySize,
                             SMEM_ATTN_TC);
        cudaFuncSetAttribute(attr_gemm_mma,
                             cudaFuncAttributeMaxDynamicSharedMemorySize,
                             SMEM_GEMM);
    }

    // fork: side stream inherits current tail of the launch stream
    cudaEventRecord(ev_fork, 0);
    cudaStreamWaitEvent(s_side, ev_fork, 0);

    // chain A (side stream): attention
    attn_tc_kernel<<<dim3(64, 2), 256, SMEM_ATTN_TC, s_side>>>(
        hidden, adj, a, out_attn);
    cudaEventRecord(ev_join, s_side);

    // chain B (main stream): bconv -> attr GEMM
    bconv_kernel<<<512, 256>>>(attr_emb);
    attr_gemm_mma<<<128, 256, SMEM_GEMM>>>(A_attr, out_attr);

    // join
    cudaStreamWaitEvent(0, ev_join, 0);
}

// round 15
// speedup vs baseline: 2.0207x; 1.1506x over previous
#include <cuda_runtime.h>
#include <cuda_bf16.h>
#include <cstdint>
#include <math.h>

#define NEG_INF_F   (-9.0e15f)

extern __shared__ char dyn_smem[];

// ============================================================================
// Helpers (battle-tested)
// ============================================================================
__device__ __forceinline__ uint32_t s2u(const void* p) {
    uint32_t a;
    asm("{ .reg .u64 t; cvta.to.shared.u64 t, %1; cvt.u32.u64 %0, t; }"
        : "=r"(a) : "l"(p));
    return a;
}
__device__ __forceinline__ void ldm_x4(uint32_t* r, uint32_t addr) {
    asm volatile("ldmatrix.sync.aligned.m8n8.x4.shared.b16 {%0,%1,%2,%3}, [%4];"
                 : "=r"(r[0]), "=r"(r[1]), "=r"(r[2]), "=r"(r[3]) : "r"(addr));
}
__device__ __forceinline__ void ldm_x4_trans(uint32_t* r, uint32_t addr) {
    asm volatile("ldmatrix.sync.aligned.m8n8.x4.trans.shared.b16 {%0,%1,%2,%3}, [%4];"
                 : "=r"(r[0]), "=r"(r[1]), "=r"(r[2]), "=r"(r[3]) : "r"(addr));
}
__device__ __forceinline__ void mma16816(float* c, const uint32_t* a, const uint32_t* b) {
    asm volatile(
        "mma.sync.aligned.m16n8k16.row.col.f32.bf16.bf16.f32 "
        "{%0,%1,%2,%3}, {%4,%5,%6,%7}, {%8,%9}, {%0,%1,%2,%3};"
        : "+f"(c[0]), "+f"(c[1]), "+f"(c[2]), "+f"(c[3])
        : "r"(a[0]), "r"(a[1]), "r"(a[2]), "r"(a[3]), "r"(b[0]), "r"(b[1]));
}
__device__ __forceinline__ uint32_t pack_bf2(float a, float b) {
    __nv_bfloat162 t = __floats2bfloat162_rn(a, b);
    return *(uint32_t*)&t;
}

// ============================================================================
// Device scratch: B^T in bf16 hi/lo, K padded to 1024 (zeros). Bt[n][k]=B[k][n]
// ============================================================================
__device__ __nv_bfloat16 g_Bh[128 * 1024];
__device__ __nv_bfloat16 g_Bl[128 * 1024];

__global__ void __launch_bounds__(256) bconv_kernel(const float* __restrict__ B) {
    int idx = blockIdx.x * 256 + threadIdx.x;   // 131072
    int n = idx & 127;
    int k = idx >> 7;
    float v = (k < 1000) ? B[k * 128 + n] : 0.f;
    __nv_bfloat16 h = __float2bfloat16(v);
    g_Bh[n * 1024 + k] = h;
    g_Bl[n * 1024 + k] = __float2bfloat16(v - __bfloat162float(h));
}

// ============================================================================
// Kernel B: attr GEMM, warp-level bf16 mma.sync split (unchanged, proven)
// ============================================================================
#define GK     1000
#define CH     64
#define NCH    16
#define PITCH  144
#define SA_H   0
#define SA_L   (64 * PITCH)
#define SB_H   (2 * 64 * PITCH)
#define SB_L   (SB_H + 128 * PITCH)
#define SMEM_GEMM (SB_L + 128 * PITCH)      // 55296

__global__ void __launch_bounds__(256)
attr_gemm_mma(const float* __restrict__ A, float* __restrict__ C) {
    char* smem = dyn_smem;
    const uint32_t sb = s2u(smem);
    const int tid  = threadIdx.x;
    const int wid  = tid >> 5;
    const int lane = tid & 31;
    const int bm   = blockIdx.x * 64;
    const int wm = wid >> 2;
    const int wn = wid & 3;

    const uint32_t aOff = (uint32_t)((lane & 15) * PITCH + (lane >> 4) * 16);
    const uint32_t bOff = (uint32_t)(((((lane >> 4) & 1) << 3) + (lane & 7)) * PITCH
                                     + ((lane >> 3) & 1) * 16);

    const int arow = tid >> 2, akseg = tid & 3;
    const int brow = tid >> 1, bseg  = tid & 1;
    const float* aptr = A + (size_t)(bm + arow) * GK;
    const __nv_bfloat16* bhp = g_Bh + brow * 1024 + bseg * 32;
    const __nv_bfloat16* blp = g_Bl + brow * 1024 + bseg * 32;

    float  as[16];
    uint4  bh4[4], bl4[4];

    {
        const float4* ap4 = (const float4*)(aptr + akseg * 16);
        #pragma unroll
        for (int i = 0; i < 4; i++) {
            float4 v = ap4[i];
            as[4*i+0] = v.x; as[4*i+1] = v.y; as[4*i+2] = v.z; as[4*i+3] = v.w;
        }
        #pragma unroll
        for (int i = 0; i < 4; i++) {
            bh4[i] = *(const uint4*)(bhp + i * 8);
            bl4[i] = *(const uint4*)(blp + i * 8);
        }
    }

    float acc[2][4][4];
    #pragma unroll
    for (int mt = 0; mt < 2; mt++)
        #pragma unroll
        for (int nt = 0; nt < 4; nt++)
            #pragma unroll
            for (int q = 0; q < 4; q++) acc[mt][nt][q] = 0.f;

    #pragma unroll 1
    for (int c = 0; c < NCH; c++) {
        if (c > 0) __syncthreads();

        {
            char* pa = smem + SA_H + arow * PITCH + akseg * 32;
            char* pl = smem + SA_L + arow * PITCH + akseg * 32;
            uint4 hv, lv;
            #pragma unroll
            for (int half = 0; half < 2; half++) {
                const float* f = as + half * 8;
                __nv_bfloat16 h0 = __float2bfloat16(f[0]), h1 = __float2bfloat16(f[1]);
                __nv_bfloat16 h2 = __float2bfloat16(f[2]), h3 = __float2bfloat16(f[3]);
                __nv_bfloat16 h4 = __float2bfloat16(f[4]), h5 = __float2bfloat16(f[5]);
                __nv_bfloat16 h6 = __float2bfloat16(f[6]), h7 = __float2bfloat16(f[7]);
                hv.x = pack_bf2(f[0], f[1]); hv.y = pack_bf2(f[2], f[3]);
                hv.z = pack_bf2(f[4], f[5]); hv.w = pack_bf2(f[6], f[7]);
                lv.x = pack_bf2(f[0]-__bfloat162float(h0), f[1]-__bfloat162float(h1));
                lv.y = pack_bf2(f[2]-__bfloat162float(h2), f[3]-__bfloat162float(h3));
                lv.z = pack_bf2(f[4]-__bfloat162float(h4), f[5]-__bfloat162float(h5));
                lv.w = pack_bf2(f[6]-__bfloat162float(h6), f[7]-__bfloat162float(h7));
                *(uint4*)(pa + half * 16) = hv;
                *(uint4*)(pl + half * 16) = lv;
            }
            char* pbh = smem + SB_H + brow * PITCH + bseg * 64;
            char* pbl = smem + SB_L + brow * PITCH + bseg * 64;
            #pragma unroll
            for (int i = 0; i < 4; i++) {
                *(uint4*)(pbh + i * 16) = bh4[i];
                *(uint4*)(pbl + i * 16) = bl4[i];
            }
        }
        __syncthreads();

        if (c + 1 < NCH) {
            const int k0 = (c + 1) * CH;
            if (c + 1 < NCH - 1) {
                const float4* ap4 = (const float4*)(aptr + k0 + akseg * 16);
                #pragma unroll
                for (int i = 0; i < 4; i++) {
                    float4 v = ap4[i];
                    as[4*i+0]=v.x; as[4*i+1]=v.y; as[4*i+2]=v.z; as[4*i+3]=v.w;
                }
            } else {
                #pragma unroll
                for (int i = 0; i < 16; i++) {
                    int kg = k0 + akseg * 16 + i;
                    as[i] = (kg < GK) ? aptr[kg] : 0.f;
                }
            }
            #pragma unroll
            for (int i = 0; i < 4; i++) {
                bh4[i] = *(const uint4*)(bhp + k0 + i * 8);
                bl4[i] = *(const uint4*)(blp + k0 + i * 8);
            }
        }

        const uint32_t aBaseH = sb + SA_H + (uint32_t)(wm * 32 * PITCH) + aOff;
        const uint32_t aBaseL = sb + SA_L + (uint32_t)(wm * 32 * PITCH) + aOff;
        const uint32_t bBaseH = sb + SB_H + (uint32_t)(wn * 32 * PITCH) + bOff;
        const uint32_t bBaseL = sb + SB_L + (uint32_t)(wn * 32 * PITCH) + bOff;

        #pragma unroll
        for (int ks = 0; ks < 4; ks++) {
            uint32_t ah[2][4], al[2][4], bhv[2][4], blv[2][4];
            #pragma unroll
            for (int mt = 0; mt < 2; mt++) {
                ldm_x4(ah[mt], aBaseH + mt * 16 * PITCH + ks * 32);
                ldm_x4(al[mt], aBaseL + mt * 16 * PITCH + ks * 32);
            }
            #pragma unroll
            for (int nh = 0; nh < 2; nh++) {
                ldm_x4(bhv[nh], bBaseH + nh * 16 * PITCH + ks * 32);
                ldm_x4(blv[nh], bBaseL + nh * 16 * PITCH + ks * 32);
            }
            #pragma unroll
            for (int mt = 0; mt < 2; mt++)
                #pragma unroll
                for (int nt = 0; nt < 4; nt++) {
                    const uint32_t* bhreg = &bhv[nt >> 1][(nt & 1) * 2];
                    const uint32_t* blreg = &blv[nt >> 1][(nt & 1) * 2];
                    mma16816(acc[mt][nt], ah[mt], bhreg);
                    mma16816(acc[mt][nt], al[mt], bhreg);
                    mma16816(acc[mt][nt], ah[mt], blreg);
                }
        }
    }

    const int g = lane >> 2, t = lane & 3;
    #pragma unroll
    for (int mt = 0; mt < 2; mt++)
        #pragma unroll
        for (int nt = 0; nt < 4; nt++) {
            int row0 = bm + wm * 32 + mt * 16 + g;
            int col  = wn * 32 + nt * 8 + t * 2;
            *(float2*)&C[(size_t)row0 * 128 + col] =
                make_float2(acc[mt][nt][0], acc[mt][nt][1]);
            *(float2*)&C[(size_t)(row0 + 8) * 128 + col] =
                make_float2(acc[mt][nt][2], acc[mt][nt][3]);
        }
}

// ============================================================================
// Kernel A: tensor-core attention, v2 (M=32 per block, 2 CTAs/SM).
//  - grid (64 batches, 4 i-quarters of 32 rows); 8 warps = 2(M16) x 4(N32).
//  - HB [j][d] bf16 hi/lo is the only H copy; AV B-frags via ldmatrix.trans.
//  - softmax in registers (shfl over t + 512B cross-warp arrays).
//  - attn probs converted to bf16 hi/lo in regs, stored to ATT (overlays AK).
// ============================================================================
#define PB      272
#define HB_H    0
#define HB_L    34816
#define AK_H    69632
#define AK_L    78336
#define ATT_H   69632
#define ATT_L   78336
#define RMAX_W  (87040 / 4)                  // 128 f32
#define RSUM_W  (87552 / 4)                  // 128 f32
#define A_SW    (88064 / 4)                  // 512 f32
#define SGN_W   (90112 / 4)                  // 256 u32
#define SMEM_ATTN_TC 91136

__global__ void __launch_bounds__(256, 2)
attn_tc_kernel(const float* __restrict__ hidden,
               const int*   __restrict__ adj,
               const float* __restrict__ a,
               float*       __restrict__ out)
{
    char*     smem  = dyn_smem;
    float*    smemf = (float*)dyn_smem;
    float*    rmax  = smemf + RMAX_W;
    float*    rsum  = smemf + RSUM_W;
    float*    a_s   = smemf + A_SW;
    uint32_t* sgn_s = (uint32_t*)dyn_smem + SGN_W;
    const uint32_t sb = s2u(smem);

    const int tid  = threadIdx.x;
    const int wid  = tid >> 5;
    const int lane = tid & 31;
    const int b    = blockIdx.x;
    const int ibase = b * 128 + blockIdx.y * 32;

    const int wm = wid >> 2, wn = wid & 3;
    const int g = lane >> 2, t = lane & 3;
    const uint32_t aOff  = (uint32_t)((lane & 15) * PB + (lane >> 4) * 16);
    const uint32_t bOff  = (uint32_t)(((((lane >> 4) & 1) << 3) + (lane & 7)) * PB
                                      + ((lane >> 3) & 1) * 16);
    const uint32_t bOffT = (uint32_t)(((lane & 7) + ((lane >> 3) & 1) * 8) * PB
                                      + ((lane >> 4) & 1) * 16);

    // ---- stage full H -> HB hi/lo (vectorized: 8 d per thread-iter) ----
    for (int q = tid; q < 2048; q += 256) {
        int j = q >> 4, db = (q & 15) * 8;
        const float* hp = hidden + (size_t)(b * 128 + j) * 128 + db;
        float4 x = *(const float4*)hp, y = *(const float4*)(hp + 4);
        float f[8] = {x.x, x.y, x.z, x.w, y.x, y.y, y.z, y.w};
        uint4 hv, lv;
        uint32_t* hw = (uint32_t*)&hv; uint32_t* lw = (uint32_t*)&lv;
        #pragma unroll
        for (int r = 0; r < 4; r++) {
            __nv_bfloat16 h0 = __float2bfloat16(f[2*r]);
            __nv_bfloat16 h1 = __float2bfloat16(f[2*r+1]);
            hw[r] = pack_bf2(f[2*r], f[2*r+1]);
            lw[r] = pack_bf2(f[2*r]   - __bfloat162float(h0),
                             f[2*r+1] - __bfloat162float(h1));
        }
        *(uint4*)(smem + HB_H + j * PB + db * 2) = hv;
        *(uint4*)(smem + HB_L + j * PB + db * 2) = lv;
    }
    for (int q = tid; q < 512; q += 256) a_s[q] = a[q];
    {   // sign table: per (k,ks,t,half): sign bits of a_k at frag d-pair
        int kk = tid >> 6, ks = (tid >> 3) & 7, tt = (tid >> 1) & 3, hf = tid & 1;
        int d0 = ks * 16 + 2 * tt + hf * 8;
        uint32_t m = (a[d0 * 4 + kk] < 0.f ? 0x8000u : 0u)
                   | (a[(d0 + 1) * 4 + kk] < 0.f ? 0x80000000u : 0u);
        sgn_s[tid] = m;
    }

    // ---- adj -> per-k 16-bit masks at this thread's fragment coords ----
    uint32_t km0 = 0, km1 = 0, km2 = 0, km3 = 0;
    #pragma unroll
    for (int nt = 0; nt < 4; nt++)
        #pragma unroll
        for (int q = 0; q < 4; q++) {
            int il = wm * 16 + g + (q >> 1) * 8;
            int j  = wn * 32 + nt * 8 + 2 * t + (q & 1);
            int av = adj[(size_t)(ibase + il) * 128 + j];
            int p  = nt * 4 + q;
            km0 |= (uint32_t)(av == 1) << p;
            km1 |= (uint32_t)(av == 2) << p;
            km2 |= (uint32_t)(av == 3) << p;
            km3 |= (uint32_t)(av == 4) << p;
        }

    float alpha[4][4];
    #pragma unroll
    for (int nt = 0; nt < 4; nt++)
        #pragma unroll
        for (int q = 0; q < 4; q++) alpha[nt][q] = NEG_INF_F;

    const int arow = tid >> 3, dseg = (tid & 7) * 16;

    // ==================== k-loop: 4 edge types ====================
    #pragma unroll 1
    for (int k = 0; k < 4; k++) {
        __syncthreads();   // staging visible / prior GEMM reads of AK done

        // stage A_k = H rows(ibase..+32) * a_k, bf16 hi/lo
        {
            const float* hrow = hidden + (size_t)(ibase + arow) * 128 + dseg;
            #pragma unroll
            for (int gq = 0; gq < 2; gq++) {
                float4 x = *(const float4*)(hrow + gq * 8);
                float4 y = *(const float4*)(hrow + gq * 8 + 4);
                float f[8] = {x.x, x.y, x.z, x.w, y.x, y.y, y.z, y.w};
                uint4 hv, lv;
                uint32_t* hw = (uint32_t*)&hv; uint32_t* lw = (uint32_t*)&lv;
                #pragma unroll
                for (int r = 0; r < 4; r++) {
                    int d0 = dseg + gq * 8 + 2 * r;
                    float f0 = f[2*r]     * a_s[d0 * 4 + k];
                    float f1 = f[2*r + 1] * a_s[(d0 + 1) * 4 + k];
                    __nv_bfloat16 h0 = __float2bfloat16(f0);
                    __nv_bfloat16 h1 = __float2bfloat16(f1);
                    hw[r] = pack_bf2(f0, f1);
                    lw[r] = pack_bf2(f0 - __bfloat162float(h0),
                                     f1 - __bfloat162float(h1));
                }
                *(uint4*)(smem + AK_H + arow * PB + (dseg + gq * 8) * 2) = hv;
                *(uint4*)(smem + AK_L + arow * PB + (dseg + gq * 8) * 2) = lv;
            }
        }
        __syncthreads();

        float Sid[4][4], Sab[4][4];
        #pragma unroll
        for (int nt = 0; nt < 4; nt++)
            #pragma unroll
            for (int q = 0; q < 4; q++) { Sid[nt][q] = 0.f; Sab[nt][q] = 0.f; }

        const uint32_t akh = sb + AK_H + (uint32_t)(wm * 16 * PB) + aOff;
        const uint32_t akl = sb + AK_L + (uint32_t)(wm * 16 * PB) + aOff;
        const uint32_t hbh = sb + HB_H + (uint32_t)(wn * 32 * PB) + bOff;
        const uint32_t hbl = sb + HB_L + (uint32_t)(wn * 32 * PB) + bOff;

        #pragma unroll
        for (int ks = 0; ks < 8; ks++) {
            uint32_t ah[4], al[4], bh[2][4], bl[2][4];
            ldm_x4(ah, akh + ks * 32);
            ldm_x4(al, akl + ks * 32);
            #pragma unroll
            for (int nh = 0; nh < 2; nh++) {
                ldm_x4(bh[nh], hbh + nh * 16 * PB + ks * 32);
                ldm_x4(bl[nh], hbl + nh * 16 * PB + ks * 32);
            }

            #pragma unroll
            for (int nt = 0; nt < 4; nt++) {
                const uint32_t* bhr = &bh[nt >> 1][(nt & 1) * 2];
                const uint32_t* blr = &bl[nt >> 1][(nt & 1) * 2];
                mma16816(Sid[nt], ah, bhr);
                mma16816(Sid[nt], al, bhr);
                mma16816(Sid[nt], ah, blr);
            }

            uint32_t m01 = sgn_s[((k * 8 + ks) * 4 + t) * 2];
            uint32_t m23 = sgn_s[((k * 8 + ks) * 4 + t) * 2 + 1];
            #pragma unroll
            for (int r = 0; r < 4; r++) {
                uint32_t mm = (r < 2) ? m01 : m23;
                al[r] = al[r] ^ (ah[r] & 0x80008000u) ^ mm;
                ah[r] = (ah[r] & 0x7FFF7FFFu) ^ mm;
            }
            #pragma unroll
            for (int nh = 0; nh < 2; nh++)
                #pragma unroll
                for (int r = 0; r < 4; r++) {
                    bl[nh][r] = bl[nh][r] ^ (bh[nh][r] & 0x80008000u);
                    bh[nh][r] = bh[nh][r] & 0x7FFF7FFFu;
                }

            #pragma unroll
            for (int nt = 0; nt < 4; nt++) {
                const uint32_t* bhr = &bh[nt >> 1][(nt & 1) * 2];
                const uint32_t* blr = &bl[nt >> 1][(nt & 1) * 2];
                mma16816(Sab[nt], ah, bhr);
                mma16816(Sab[nt], al, bhr);
                mma16816(Sab[nt], ah, blr);
            }
        }

        uint32_t mk = (k == 0) ? km0 : (k == 1) ? km1 : (k == 2) ? km2 : km3;
        #pragma unroll
        for (int nt = 0; nt < 4; nt++)
            #pragma unroll
            for (int q = 0; q < 4; q++) {
                float combo = fmaf(0.6f, Sid[nt][q], 0.4f * Sab[nt][q]);
                int p = nt * 4 + q;
                if ((mk >> p) & 1u) alpha[nt][q] = combo;
            }
    }

    // ---- softmax in registers ----
    float mloc[2];
    #pragma unroll
    for (int qh = 0; qh < 2; qh++) {
        float m = NEG_INF_F;
        #pragma unroll
        for (int nt = 0; nt < 4; nt++) {
            m = fmaxf(m, alpha[nt][qh * 2 + 0]);
            m = fmaxf(m, alpha[nt][qh * 2 + 1]);
        }
        m = fmaxf(m, __shfl_xor_sync(0xffffffffu, m, 1));
        m = fmaxf(m, __shfl_xor_sync(0xffffffffu, m, 2));
        mloc[qh] = m;
    }
    if (t == 0) {
        rmax[(wm * 16 + 0 * 8 + g) * 4 + wn] = mloc[0];
        rmax[(wm * 16 + 1 * 8 + g) * 4 + wn] = mloc[1];
    }
    __syncthreads();

    float inv[2];
    #pragma unroll
    for (int qh = 0; qh < 2; qh++) {
        int row = wm * 16 + qh * 8 + g;
        float m = fmaxf(fmaxf(rmax[row * 4 + 0], rmax[row * 4 + 1]),
                        fmaxf(rmax[row * 4 + 2], rmax[row * 4 + 3]));
        float s = 0.f;
        #pragma unroll
        for (int nt = 0; nt < 4; nt++) {
            alpha[nt][qh * 2 + 0] = __expf(alpha[nt][qh * 2 + 0] - m);
            alpha[nt][qh * 2 + 1] = __expf(alpha[nt][qh * 2 + 1] - m);
            s += alpha[nt][qh * 2 + 0] + alpha[nt][qh * 2 + 1];
        }
        s += __shfl_xor_sync(0xffffffffu, s, 1);
        s += __shfl_xor_sync(0xffffffffu, s, 2);
        if (t == 0) rsum[row * 4 + wn] = s;
        mloc[qh] = 0.f;   // reuse slot (unused after)
    }
    __syncthreads();
    #pragma unroll
    for (int qh = 0; qh < 2; qh++) {
        int row = wm * 16 + qh * 8 + g;
        float s = (rsum[row * 4 + 0] + rsum[row * 4 + 1]) +
                  (rsum[row * 4 + 2] + rsum[row * 4 + 3]);
        inv[qh] = 1.f / s;
    }

    // ---- write attn probs as bf16 hi/lo ATT tiles (overlay AK) ----
    #pragma unroll
    for (int qh = 0; qh < 2; qh++) {
        int row = wm * 16 + qh * 8 + g;
        #pragma unroll
        for (int nt = 0; nt < 4; nt++) {
            float p0 = alpha[nt][qh * 2 + 0] * inv[qh];
            float p1 = alpha[nt][qh * 2 + 1] * inv[qh];
            __nv_bfloat16 h0 = __float2bfloat16(p0);
            __nv_bfloat16 h1 = __float2bfloat16(p1);
            uint32_t hw = pack_bf2(p0, p1);
            uint32_t lw = pack_bf2(p0 - __bfloat162float(h0),
                                   p1 - __bfloat162float(h1));
            uint32_t off = (uint32_t)(row * PB + (wn * 32 + nt * 8 + 2 * t) * 2);
            *(uint32_t*)(smem + ATT_H + off) = hw;
            *(uint32_t*)(smem + ATT_L + off) = lw;
        }
    }
    __syncthreads();

    // ---- AV GEMM: out = attn @ H; B-frags via trans ldmatrix from HB ----
    float O[4][4];
    #pragma unroll
    for (int nt = 0; nt < 4; nt++)
        #pragma unroll
        for (int q = 0; q < 4; q++) O[nt][q] = 0.f;

    const uint32_t ath = sb + ATT_H + (uint32_t)(wm * 16 * PB) + aOff;
    const uint32_t atl = sb + ATT_L + (uint32_t)(wm * 16 * PB) + aOff;

    #pragma unroll
    for (int ks = 0; ks < 8; ks++) {
        uint32_t ah[4], al[4], bh[2][4], bl[2][4];
        ldm_x4(ah, ath + ks * 32);
        ldm_x4(al, atl + ks * 32);
        #pragma unroll
        for (int nh = 0; nh < 2; nh++) {
            uint32_t base = (uint32_t)(ks * 16 * PB + (wn * 32 + nh * 16) * 2) + bOffT;
            ldm_x4_trans(bh[nh], sb + HB_H + base);
            ldm_x4_trans(bl[nh], sb + HB_L + base);
        }
        #pragma unroll
        for (int nt = 0; nt < 4; nt++) {
            const uint32_t* bhr = &bh[nt >> 1][(nt & 1) * 2];
            const uint32_t* blr = &bl[nt >> 1][(nt & 1) * 2];
            mma16816(O[nt], ah, bhr);
            mma16816(O[nt], al, bhr);
            mma16816(O[nt], ah, blr);
        }
    }

    #pragma unroll
    for (int nt = 0; nt < 4; nt++) {
        int row0 = ibase + wm * 16 + g;
        int col  = wn * 32 + nt * 8 + t * 2;
        *(float2*)&out[(size_t)row0 * 128 + col] =
            make_float2(O[nt][0], O[nt][1]);
        *(float2*)&out[(size_t)(row0 + 8) * 128 + col] =
            make_float2(O[nt][2], O[nt][3]);
    }
}

// ============================================================================
// Launch: fork/join — attn_tc overlaps bconv -> attr_gemm.
// ============================================================================
extern "C" void kernel_launch(void* const* d_in, const int* in_sizes, int n_in,
                              void* d_out, int out_size)
{
    const float* hidden   = (const float*)d_in[0];  // [64,128,128]
    const int*   adj      = (const int*)  d_in[1];  // [64,128,128]
    const float* a        = (const float*)d_in[2];  // [128,4]
    const float* A_attr   = (const float*)d_in[3];  // [64,128,1000]
    const float* attr_emb = (const float*)d_in[4];  // [1000,128]

    float* out       = (float*)d_out;
    float* out_attn  = out;                   // output    [64,128,128]
    float* out_attr  = out + 64 * 128 * 128;  // attr_sess [64,128,128]

    static cudaStream_t s_side = nullptr;
    static cudaEvent_t  ev_fork = nullptr, ev_join = nullptr;
    if (s_side == nullptr) {
        cudaStreamCreateWithFlags(&s_side, cudaStreamNonBlocking);
        cudaEventCreateWithFlags(&ev_fork, cudaEventDisableTiming);
        cudaEventCreateWithFlags(&ev_join, cudaEventDisableTiming);
        cudaFuncSetAttribute(attn_tc_kernel,
                             cudaFuncAttributeMaxDynamicSharedMemorySize,
                             SMEM_ATTN_TC);
        cudaFuncSetAttribute(attr_gemm_mma,
                             cudaFuncAttributeMaxDynamicSharedMemorySize,
                             SMEM_GEMM);
    }

    cudaEventRecord(ev_fork, 0);
    cudaStreamWaitEvent(s_side, ev_fork, 0);

    attn_tc_kernel<<<dim3(64, 4), 256, SMEM_ATTN_TC, s_side>>>(
        hidden, adj, a, out_attn);
    cudaEventRecord(ev_join, s_side);

    bconv_kernel<<<512, 256>>>(attr_emb);
    attr_gemm_mma<<<128, 256, SMEM_GEMM>>>(A_attr, out_attr);

    cudaStreamWaitEvent(0, ev_join, 0);
}